// round 7
// baseline (speedup 1.0000x reference)
#include <cuda_runtime.h>
#include <cuda_bf16.h>
#include <cstdint>

#define NN 100000
#define NE 1600000
#define F0 256
#define F1 128
#define F2 64
#define NBLK_SCAN 98   // ceil(NN/1024)

// ---- scratch (device globals; no allocation allowed) ----
__device__ float g_h1[NN * F1];     // x @ W1
__device__ float g_hr[NN * F1];     // relu(agg1 + b1)  (input to GEMM2)
__device__ float g_h2[NN * F2];     // hr @ W2
__device__ float g_dinv[NN];
__device__ int   g_deg[NN];
__device__ int   g_rowstart[NN];
__device__ int   g_cursor[NN];
__device__ int   g_csr[NE];
__device__ int   g_src[NE];
__device__ int   g_dst[NE];
__device__ int   g_is32;
__device__ int   g_part[128];
__device__ int   g_base[128];
// W split into bf16 hi/lo (row-major [k][n])
__device__ __align__(16) __nv_bfloat16 g_w1h[F0 * F1];
__device__ __align__(16) __nv_bfloat16 g_w1l[F0 * F1];
__device__ __align__(16) __nv_bfloat16 g_w2h[F1 * F2];
__device__ __align__(16) __nv_bfloat16 g_w2l[F1 * F2];

// ================= mma.sync helpers (sm_80+ PTX; safe on base sm_103) =========
__device__ __forceinline__ uint32_t s2u(const void* p) {
    uint32_t a;
    asm("{ .reg .u64 t; cvta.to.shared.u64 t, %1; cvt.u32.u64 %0, t; }" : "=r"(a) : "l"(p));
    return a;
}

__device__ __forceinline__ void ldsm4(uint32_t* r, uint32_t a) {
    asm volatile("ldmatrix.sync.aligned.m8n8.x4.shared.b16 {%0,%1,%2,%3}, [%4];"
                 : "=r"(r[0]), "=r"(r[1]), "=r"(r[2]), "=r"(r[3]) : "r"(a));
}
__device__ __forceinline__ void ldsm4t(uint32_t* r, uint32_t a) {
    asm volatile("ldmatrix.sync.aligned.m8n8.x4.trans.shared.b16 {%0,%1,%2,%3}, [%4];"
                 : "=r"(r[0]), "=r"(r[1]), "=r"(r[2]), "=r"(r[3]) : "r"(a));
}
__device__ __forceinline__ void mma16816(float* c, const uint32_t* a,
                                         uint32_t b0, uint32_t b1) {
    asm volatile("mma.sync.aligned.m16n8k16.row.col.f32.bf16.bf16.f32 "
                 "{%0,%1,%2,%3}, {%4,%5,%6,%7}, {%8,%9}, {%0,%1,%2,%3};"
                 : "+f"(c[0]), "+f"(c[1]), "+f"(c[2]), "+f"(c[3])
                 : "r"(a[0]), "r"(a[1]), "r"(a[2]), "r"(a[3]), "r"(b0), "r"(b1));
}

__device__ __forceinline__ uint32_t pack2(__nv_bfloat16 a, __nv_bfloat16 b) {
    return (uint32_t)__bfloat16_as_ushort(a) | ((uint32_t)__bfloat16_as_ushort(b) << 16);
}

// ---------------- edge dtype detect + convert (+fused degree count) ----------------
__global__ void k_detect(const void* __restrict__ ei) {
    if (blockIdx.x == 0 && threadIdx.x == 0) {
        const long long* e64 = (const long long*)ei;
        int ok64 = 1;
        for (int i = 0; i < 128; i++) {
            long long v = e64[i];
            if (v < 0 || v >= NN) { ok64 = 0; break; }
        }
        g_is32 = ok64 ? 0 : 1;
    }
}

__global__ void k_convert(const void* __restrict__ ei) {
    int i = blockIdx.x * blockDim.x + threadIdx.x;
    if (i >= 2 * NE) return;
    int v;
    if (g_is32) v = ((const int*)ei)[i];
    else        v = (int)((const long long*)ei)[i];
    if (i < NE) g_src[i] = v;
    else {
        g_dst[i - NE] = v;
        if (v >= 0 && v < NN) atomicAdd(&g_deg[v], 1);   // fused degree count
    }
}

__global__ void k_deg_init() {
    int i = blockIdx.x * blockDim.x + threadIdx.x;
    if (i < NN) g_deg[i] = 1;   // +1 self loop baked in
}

__global__ void k_dinv() {
    int i = blockIdx.x * blockDim.x + threadIdx.x;
    if (i < NN) g_dinv[i] = rsqrtf((float)g_deg[i]);
}

// ---------------- W split to bf16 hi/lo ----------------
__global__ void k_wsplit(const float* __restrict__ W1, const float* __restrict__ W2) {
    int i = blockIdx.x * blockDim.x + threadIdx.x;
    if (i < F0 * F1) {
        float v = W1[i];
        __nv_bfloat16 h = __float2bfloat16(v);
        g_w1h[i] = h;
        g_w1l[i] = __float2bfloat16(v - __bfloat162float(h));
    } else if (i < F0 * F1 + F1 * F2) {
        int j = i - F0 * F1;
        float v = W2[j];
        __nv_bfloat16 h = __float2bfloat16(v);
        g_w2h[j] = h;
        g_w2l[j] = __float2bfloat16(v - __bfloat162float(h));
    }
}

// ---------------- CSR build: 3-phase scan of (deg-1), then cursor fill ----------------
__global__ void k_scan_partial() {
    __shared__ int s[1024];
    int t = threadIdx.x;
    int i = blockIdx.x * 1024 + t;
    int v = (i < NN) ? (g_deg[i] - 1) : 0;
    s[t] = v;
    __syncthreads();
    for (int off = 512; off > 0; off >>= 1) {
        if (t < off) s[t] += s[t + off];
        __syncthreads();
    }
    if (t == 0) g_part[blockIdx.x] = s[0];
}

__global__ void k_scan_base() {
    __shared__ int s[128];
    int t = threadIdx.x;
    int v = (t < NBLK_SCAN) ? g_part[t] : 0;
    s[t] = v;
    __syncthreads();
    for (int off = 1; off < 128; off <<= 1) {
        int u = (t >= off) ? s[t - off] : 0;
        __syncthreads();
        s[t] += u;
        __syncthreads();
    }
    if (t < NBLK_SCAN) g_base[t] = s[t] - v;  // exclusive
}

__global__ void k_scan_write() {
    __shared__ int s[1024];
    int t = threadIdx.x;
    int i = blockIdx.x * 1024 + t;
    int v = (i < NN) ? (g_deg[i] - 1) : 0;
    s[t] = v;
    __syncthreads();
    for (int off = 1; off < 1024; off <<= 1) {
        int u = (t >= off) ? s[t - off] : 0;
        __syncthreads();
        s[t] += u;
        __syncthreads();
    }
    if (i < NN) {
        int start = g_base[blockIdx.x] + s[t] - v;
        g_rowstart[i] = start;
        g_cursor[i]   = start;
    }
}

__global__ void k_fill() {
    int i = blockIdx.x * blockDim.x + threadIdx.x;
    if (i < NE) {
        int d = g_dst[i];
        if (d < 0 || d >= NN) return;
        int pos = atomicAdd(&g_cursor[d], 1);
        if (pos >= 0 && pos < NE) g_csr[pos] = g_src[i];
    }
}

// =======================================================================
// Split-bf16 mma.sync GEMM:  Out[M,NC] = A[M,KT] @ W[KT,NC]
// fp32 A is split to bf16 hi/lo during smem staging; W pre-split in globals.
// 3 MMA passes (hi*hi + hi*lo + lo*hi) recover ~fp32 precision (~1e-5).
// CTA: 128 rows x NC cols, 256 threads = 8 warps (4 M x 2 N).
// K chunked at 32 (2 k16 steps per chunk).
// MODE 1: A=x,   Out=g_h1, W=g_w1*.   MODE 2: A=g_hr, Out=g_h2, W=g_w2*.
// =======================================================================
template<int NC, int KT, int MODE>
__global__ void __launch_bounds__(256, 2) k_mma(const float* __restrict__ Ain) {
    constexpr int KC   = 32;
    constexpr int AST  = 40;        // bf16 per A smem row (32 + 8 pad) -> 80B, conflict-free ldsm
    constexpr int BST  = NC + 8;    // bf16 per B smem row -> (NC*2+16)B, conflict-free ldsm.trans
    constexpr int NWN  = NC / 2;    // cols per warp
    constexpr int NT8  = NWN / 8;   // n8 tiles per warp
    constexpr int NT16 = NWN / 16;  // ldmatrix-x4 B groups per warp
    constexpr int NC8  = NC / 8;    // uint4 per B row

    __shared__ __align__(16) __nv_bfloat16 Ah[128 * AST];
    __shared__ __align__(16) __nv_bfloat16 Al[128 * AST];
    __shared__ __align__(16) __nv_bfloat16 Bh[KC * BST];
    __shared__ __align__(16) __nv_bfloat16 Bl[KC * BST];

    const float* __restrict__ A = (MODE == 1) ? Ain : (const float*)g_hr;
    float* __restrict__ Out     = (MODE == 1) ? g_h1 : g_h2;
    const __nv_bfloat16* __restrict__ WH = (MODE == 1) ? g_w1h : g_w2h;
    const __nv_bfloat16* __restrict__ WL = (MODE == 1) ? g_w1l : g_w2l;

    const int tid = threadIdx.x, lane = tid & 31, wid = tid >> 5;
    const int warp_m = wid & 3, warp_n = wid >> 2;
    const int rbase = blockIdx.x * 128;

    const uint32_t ah_b = s2u(Ah), al_b = s2u(Al);
    const uint32_t bh_b = s2u(Bh), bl_b = s2u(Bl);

    float acc[2][NT8][4];
    #pragma unroll
    for (int a = 0; a < 2; a++)
        #pragma unroll
        for (int b = 0; b < NT8; b++)
            #pragma unroll
            for (int c = 0; c < 4; c++) acc[a][b][c] = 0.f;

    // per-lane ldmatrix address components
    const int a_row = (lane & 15);              // + m0
    const int a_col = 8 * (lane >> 4);          // + k16
    const int b_row = (lane & 15);              // + k16
    const int b_col = 8 * (lane >> 4);          // + n0

    const float4* av = (const float4*)A;
    constexpr int ROWF4 = KT / 4;

    for (int ch = 0; ch < KT / KC; ch++) {
        const int c0 = ch * KC;

        // ---- stage A chunk: 128 x 32 fp32 -> bf16 hi/lo ----
        #pragma unroll
        for (int i = 0; i < 4; i++) {
            int idx = tid + i * 256;            // 0..1023
            int r = idx >> 3;
            int f = idx & 7;                    // float4 within chunk
            float4 v = make_float4(0.f, 0.f, 0.f, 0.f);
            int gr = rbase + r;
            if (gr < NN) v = av[(size_t)gr * ROWF4 + (c0 >> 2) + f];

            __nv_bfloat16 hx = __float2bfloat16(v.x), hy = __float2bfloat16(v.y);
            __nv_bfloat16 hz = __float2bfloat16(v.z), hw = __float2bfloat16(v.w);
            uint2 hp, lp;
            hp.x = pack2(hx, hy);
            hp.y = pack2(hz, hw);
            lp.x = pack2(__float2bfloat16(v.x - __bfloat162float(hx)),
                         __float2bfloat16(v.y - __bfloat162float(hy)));
            lp.y = pack2(__float2bfloat16(v.z - __bfloat162float(hz)),
                         __float2bfloat16(v.w - __bfloat162float(hw)));
            int e = r * AST + f * 4;
            *(uint2*)&Ah[e] = hp;
            *(uint2*)&Al[e] = lp;
        }

        // ---- stage B chunk: 32 x NC bf16 hi/lo (plain copy) ----
        #pragma unroll
        for (int i = 0; i < (KC * NC8) / 256; i++) {
            int idx = tid + i * 256;
            int k = idx / NC8, n8 = idx % NC8;
            int e = k * BST + n8 * 8;
            size_t ge = (size_t)(c0 + k) * NC + n8 * 8;
            *(uint4*)&Bh[e] = *(const uint4*)&WH[ge];
            *(uint4*)&Bl[e] = *(const uint4*)&WL[ge];
        }
        __syncthreads();

        // ---- compute: 2 k16 steps ----
        #pragma unroll
        for (int ks = 0; ks < 2; ks++) {
            const int k16 = ks * 16;
            uint32_t afh[2][4], afl[2][4];
            #pragma unroll
            for (int mi = 0; mi < 2; mi++) {
                uint32_t off = (uint32_t)(((warp_m * 32 + mi * 16 + a_row) * AST
                                           + k16 + a_col) * 2);
                ldsm4(afh[mi], ah_b + off);
                ldsm4(afl[mi], al_b + off);
            }
            #pragma unroll
            for (int ni = 0; ni < NT16; ni++) {
                uint32_t off = (uint32_t)(((k16 + b_row) * BST
                                           + warp_n * NWN + ni * 16 + b_col) * 2);
                uint32_t bfh[4], bfl[4];
                ldsm4t(bfh, bh_b + off);
                ldsm4t(bfl, bl_b + off);
                #pragma unroll
                for (int mi = 0; mi < 2; mi++) {
                    mma16816(acc[mi][2 * ni],     afh[mi], bfh[0], bfh[1]);  // hi*hi
                    mma16816(acc[mi][2 * ni + 1], afh[mi], bfh[2], bfh[3]);
                    mma16816(acc[mi][2 * ni],     afh[mi], bfl[0], bfl[1]);  // hi*lo
                    mma16816(acc[mi][2 * ni + 1], afh[mi], bfl[2], bfl[3]);
                    mma16816(acc[mi][2 * ni],     afl[mi], bfh[0], bfh[1]);  // lo*hi
                    mma16816(acc[mi][2 * ni + 1], afl[mi], bfh[2], bfh[3]);
                }
            }
        }
        __syncthreads();
    }

    // ---- epilogue: fp32 write (c0,c1 are contiguous cols -> float2) ----
    const int g = lane >> 2, tig = lane & 3;
    #pragma unroll
    for (int mi = 0; mi < 2; mi++) {
        int row0 = rbase + warp_m * 32 + mi * 16 + g;
        #pragma unroll
        for (int ni = 0; ni < NT8; ni++) {
            int col = warp_n * NWN + ni * 8 + tig * 2;
            if (row0 < NN)
                *(float2*)&Out[(size_t)row0 * NC + col] =
                    make_float2(acc[mi][ni][0], acc[mi][ni][1]);
            if (row0 + 8 < NN)
                *(float2*)&Out[(size_t)(row0 + 8) * NC + col] =
                    make_float2(acc[mi][ni][2], acc[mi][ni][3]);
        }
    }
}

// ---------------- Layer-1 aggregation (gather, no atomics) + bias + ReLU ----------------
__global__ void k_agg1(const float* __restrict__ b1) {
    int gw   = (blockIdx.x * blockDim.x + threadIdx.x) >> 5;
    int lane = threadIdx.x & 31;
    if (gw >= NN) return;

    int start = g_rowstart[gw];
    int cnt   = g_deg[gw] - 1;
    float dd  = g_dinv[gw];

    const float4* h1v = (const float4*)g_h1;
    float4 acc = make_float4(0.f, 0.f, 0.f, 0.f);

    int i = 0;
    for (; i + 1 < cnt; i += 2) {
        int s0 = g_csr[start + i];
        int s1 = g_csr[start + i + 1];
        float c0 = dd * g_dinv[s0];
        float c1 = dd * g_dinv[s1];
        float4 v0 = h1v[(size_t)s0 * 32 + lane];
        float4 v1 = h1v[(size_t)s1 * 32 + lane];
        acc.x += c0 * v0.x + c1 * v1.x;
        acc.y += c0 * v0.y + c1 * v1.y;
        acc.z += c0 * v0.z + c1 * v1.z;
        acc.w += c0 * v0.w + c1 * v1.w;
    }
    if (i < cnt) {
        int s0 = g_csr[start + i];
        float c0 = dd * g_dinv[s0];
        float4 v0 = h1v[(size_t)s0 * 32 + lane];
        acc.x += c0 * v0.x; acc.y += c0 * v0.y;
        acc.z += c0 * v0.z; acc.w += c0 * v0.w;
    }

    float c2 = dd * dd;
    float4 hv = h1v[(size_t)gw * 32 + lane];
    float4 bb = ((const float4*)b1)[lane];
    float4 o;
    o.x = fmaxf(acc.x + c2 * hv.x + bb.x, 0.f);
    o.y = fmaxf(acc.y + c2 * hv.y + bb.y, 0.f);
    o.z = fmaxf(acc.z + c2 * hv.z + bb.z, 0.f);
    o.w = fmaxf(acc.w + c2 * hv.w + bb.w, 0.f);
    ((float4*)g_hr)[(size_t)gw * 32 + lane] = o;
}

// ---------------- Layer-2 aggregation + bias + fused log_softmax ----------------
__global__ void k_agg2(const float* __restrict__ b2, float* __restrict__ out) {
    int gw   = (blockIdx.x * blockDim.x + threadIdx.x) >> 5;
    int lane = threadIdx.x & 31;
    if (gw >= NN) return;

    int start = g_rowstart[gw];
    int cnt   = g_deg[gw] - 1;
    float dd  = g_dinv[gw];

    const float2* h2v = (const float2*)g_h2;
    float2 acc = make_float2(0.f, 0.f);

    int i = 0;
    for (; i + 1 < cnt; i += 2) {
        int s0 = g_csr[start + i];
        int s1 = g_csr[start + i + 1];
        float c0 = dd * g_dinv[s0];
        float c1 = dd * g_dinv[s1];
        float2 v0 = h2v[(size_t)s0 * 32 + lane];
        float2 v1 = h2v[(size_t)s1 * 32 + lane];
        acc.x += c0 * v0.x + c1 * v1.x;
        acc.y += c0 * v0.y + c1 * v1.y;
    }
    if (i < cnt) {
        int s0 = g_csr[start + i];
        float c0 = dd * g_dinv[s0];
        float2 v0 = h2v[(size_t)s0 * 32 + lane];
        acc.x += c0 * v0.x;
        acc.y += c0 * v0.y;
    }

    float c2 = dd * dd;
    float2 hv = h2v[(size_t)gw * 32 + lane];
    float2 bb = ((const float2*)b2)[lane];
    float a = acc.x + c2 * hv.x + bb.x;
    float b = acc.y + c2 * hv.y + bb.y;

    float m = fmaxf(a, b);
    #pragma unroll
    for (int off = 16; off > 0; off >>= 1)
        m = fmaxf(m, __shfl_xor_sync(0xFFFFFFFFu, m, off));
    float s = expf(a - m) + expf(b - m);
    #pragma unroll
    for (int off = 16; off > 0; off >>= 1)
        s += __shfl_xor_sync(0xFFFFFFFFu, s, off);
    float l = m + logf(s);

    float2 o = make_float2(a - l, b - l);
    ((float2*)out)[(size_t)gw * 32 + lane] = o;
}

// ---------------- launch ----------------
extern "C" void kernel_launch(void* const* d_in, const int* in_sizes, int n_in,
                              void* d_out, int out_size) {
    const float* x   = (const float*)d_in[0];
    const void*  ei  = (const void*)d_in[1];
    const float* W1  = (const float*)d_in[2];
    const float* b1  = (const float*)d_in[3];
    const float* W2  = (const float*)d_in[4];
    const float* b2  = (const float*)d_in[5];
    float*       out = (float*)d_out;

    // edge index: detect int32 vs int64 on-device, materialize as int (+degree)
    k_deg_init<<<(NN + 255) / 256, 256>>>();
    k_detect<<<1, 32>>>(ei);
    k_convert<<<(2 * NE + 255) / 256, 256>>>(ei);
    k_dinv<<<(NN + 255) / 256, 256>>>();
    k_wsplit<<<(F0 * F1 + F1 * F2 + 255) / 256, 256>>>(W1, W2);

    // CSR build
    k_scan_partial<<<NBLK_SCAN, 1024>>>();
    k_scan_base<<<1, 128>>>();
    k_scan_write<<<NBLK_SCAN, 1024>>>();
    k_fill<<<(NE + 255) / 256, 256>>>();

    const int NTILE = (NN + 127) / 128;

    // layer 1: split-bf16 tensor-core GEMM + gather agg (+bias+relu)
    k_mma<F1, F0, 1><<<NTILE, 256>>>(x);
    k_agg1<<<(NN * 32 + 255) / 256, 256>>>(b1);

    // layer 2: GEMM + gather agg (+bias + fused log_softmax)
    k_mma<F2, F1, 2><<<NTILE, 256>>>(x);
    k_agg2<<<(NN * 32 + 255) / 256, 256>>>(b2, out);
}

// round 8
// speedup vs baseline: 1.1220x; 1.1220x over previous
#include <cuda_runtime.h>
#include <cuda_bf16.h>
#include <cuda_fp16.h>
#include <cstdint>

#define NN 100000
#define NE 1600000
#define F0 256
#define F1 128
#define F2 64
#define NBLK_SCAN 98   // ceil(NN/1024)

// ---- scratch (device globals; no allocation allowed) ----
__device__ __align__(16) __half g_h1[NN * F1];   // x @ W1          (fp16 gather operand)
__device__ float g_hr[NN * F1];                  // relu(agg1+b1)   (fp32: GEMM2 input)
__device__ __align__(16) __half g_h2[NN * F2];   // hr @ W2         (fp16 gather operand)
__device__ float g_dinv[NN];
__device__ int   g_deg[NN];
__device__ int   g_rowstart[NN];
__device__ int   g_cursor[NN];
__device__ int   g_csr[NE];
__device__ int   g_dst[NE];
__device__ int   g_is32;
__device__ int   g_part[128];
__device__ int   g_base[128];
// W split into bf16 hi/lo (row-major [k][n])
__device__ __align__(16) __nv_bfloat16 g_w1h[F0 * F1];
__device__ __align__(16) __nv_bfloat16 g_w1l[F0 * F1];
__device__ __align__(16) __nv_bfloat16 g_w2h[F1 * F2];
__device__ __align__(16) __nv_bfloat16 g_w2l[F1 * F2];

// ================= mma.sync helpers (sm_80+ PTX; safe on base sm_103) =========
__device__ __forceinline__ uint32_t s2u(const void* p) {
    uint32_t a;
    asm("{ .reg .u64 t; cvta.to.shared.u64 t, %1; cvt.u32.u64 %0, t; }" : "=r"(a) : "l"(p));
    return a;
}

__device__ __forceinline__ void ldsm4(uint32_t* r, uint32_t a) {
    asm volatile("ldmatrix.sync.aligned.m8n8.x4.shared.b16 {%0,%1,%2,%3}, [%4];"
                 : "=r"(r[0]), "=r"(r[1]), "=r"(r[2]), "=r"(r[3]) : "r"(a));
}
__device__ __forceinline__ void ldsm4t(uint32_t* r, uint32_t a) {
    asm volatile("ldmatrix.sync.aligned.m8n8.x4.trans.shared.b16 {%0,%1,%2,%3}, [%4];"
                 : "=r"(r[0]), "=r"(r[1]), "=r"(r[2]), "=r"(r[3]) : "r"(a));
}
__device__ __forceinline__ void mma16816(float* c, const uint32_t* a,
                                         uint32_t b0, uint32_t b1) {
    asm volatile("mma.sync.aligned.m16n8k16.row.col.f32.bf16.bf16.f32 "
                 "{%0,%1,%2,%3}, {%4,%5,%6,%7}, {%8,%9}, {%0,%1,%2,%3};"
                 : "+f"(c[0]), "+f"(c[1]), "+f"(c[2]), "+f"(c[3])
                 : "r"(a[0]), "r"(a[1]), "r"(a[2]), "r"(a[3]), "r"(b0), "r"(b1));
}

__device__ __forceinline__ uint32_t pack2(__nv_bfloat16 a, __nv_bfloat16 b) {
    return (uint32_t)__bfloat16_as_ushort(a) | ((uint32_t)__bfloat16_as_ushort(b) << 16);
}

// ---------------- edge dtype detect + dst convert (+fused degree count) ----------------
__global__ void k_detect(const void* __restrict__ ei) {
    if (blockIdx.x == 0 && threadIdx.x == 0) {
        const long long* e64 = (const long long*)ei;
        int ok64 = 1;
        for (int i = 0; i < 128; i++) {
            long long v = e64[i];
            if (v < 0 || v >= NN) { ok64 = 0; break; }
        }
        g_is32 = ok64 ? 0 : 1;
    }
}

__global__ void k_convert(const void* __restrict__ ei) {
    int i = blockIdx.x * blockDim.x + threadIdx.x;
    if (i >= NE) return;
    int v;
    if (g_is32) v = ((const int*)ei)[NE + i];
    else        v = (int)((const long long*)ei)[NE + i];
    g_dst[i] = v;
    if (v >= 0 && v < NN) atomicAdd(&g_deg[v], 1);   // fused degree count
}

__global__ void k_deg_init() {
    int i = blockIdx.x * blockDim.x + threadIdx.x;
    if (i < NN) g_deg[i] = 1;   // +1 self loop baked in
}

__global__ void k_dinv() {
    int i = blockIdx.x * blockDim.x + threadIdx.x;
    if (i < NN) g_dinv[i] = rsqrtf((float)g_deg[i]);
}

// ---------------- W split to bf16 hi/lo ----------------
__global__ void k_wsplit(const float* __restrict__ W1, const float* __restrict__ W2) {
    int i = blockIdx.x * blockDim.x + threadIdx.x;
    if (i < F0 * F1) {
        float v = W1[i];
        __nv_bfloat16 h = __float2bfloat16(v);
        g_w1h[i] = h;
        g_w1l[i] = __float2bfloat16(v - __bfloat162float(h));
    } else if (i < F0 * F1 + F1 * F2) {
        int j = i - F0 * F1;
        float v = W2[j];
        __nv_bfloat16 h = __float2bfloat16(v);
        g_w2h[j] = h;
        g_w2l[j] = __float2bfloat16(v - __bfloat162float(h));
    }
}

// ---------------- CSR build: 3-phase scan of (deg-1), then cursor fill ----------------
__global__ void k_scan_partial() {
    __shared__ int s[1024];
    int t = threadIdx.x;
    int i = blockIdx.x * 1024 + t;
    int v = (i < NN) ? (g_deg[i] - 1) : 0;
    s[t] = v;
    __syncthreads();
    for (int off = 512; off > 0; off >>= 1) {
        if (t < off) s[t] += s[t + off];
        __syncthreads();
    }
    if (t == 0) g_part[blockIdx.x] = s[0];
}

__global__ void k_scan_base() {
    __shared__ int s[128];
    int t = threadIdx.x;
    int v = (t < NBLK_SCAN) ? g_part[t] : 0;
    s[t] = v;
    __syncthreads();
    for (int off = 1; off < 128; off <<= 1) {
        int u = (t >= off) ? s[t - off] : 0;
        __syncthreads();
        s[t] += u;
        __syncthreads();
    }
    if (t < NBLK_SCAN) g_base[t] = s[t] - v;  // exclusive
}

__global__ void k_scan_write() {
    __shared__ int s[1024];
    int t = threadIdx.x;
    int i = blockIdx.x * 1024 + t;
    int v = (i < NN) ? (g_deg[i] - 1) : 0;
    s[t] = v;
    __syncthreads();
    for (int off = 1; off < 1024; off <<= 1) {
        int u = (t >= off) ? s[t - off] : 0;
        __syncthreads();
        s[t] += u;
        __syncthreads();
    }
    if (i < NN) {
        int start = g_base[blockIdx.x] + s[t] - v;
        g_rowstart[i] = start;
        g_cursor[i]   = start;
    }
}

__global__ void k_fill(const void* __restrict__ ei) {
    int i = blockIdx.x * blockDim.x + threadIdx.x;
    if (i < NE) {
        int d = g_dst[i];
        if (d < 0 || d >= NN) return;
        int s;
        if (g_is32) s = ((const int*)ei)[i];
        else        s = (int)((const long long*)ei)[i];
        int pos = atomicAdd(&g_cursor[d], 1);
        if (pos >= 0 && pos < NE) g_csr[pos] = s;
    }
}

// =======================================================================
// Split-bf16 mma.sync GEMM:  Out[M,NC](fp16) = A[M,KT](fp32) @ W[KT,NC]
// fp32 A split to bf16 hi/lo during smem staging; W pre-split in globals.
// 3 MMA passes (hi*hi + hi*lo + lo*hi) give ~fp32 precision.
// CTA: 128 rows x NC cols, 256 threads = 8 warps (4 M x 2 N). K chunk 32.
// MODE 1: A=x,   Out=g_h1, W=g_w1*.   MODE 2: A=g_hr, Out=g_h2, W=g_w2*.
// =======================================================================
template<int NC, int KT, int MODE>
__global__ void __launch_bounds__(256, 2) k_mma(const float* __restrict__ Ain) {
    constexpr int KC   = 32;
    constexpr int AST  = 40;        // bf16 per A smem row (32 + 8 pad)
    constexpr int BST  = NC + 8;
    constexpr int NWN  = NC / 2;
    constexpr int NT8  = NWN / 8;
    constexpr int NT16 = NWN / 16;
    constexpr int NC8  = NC / 8;

    __shared__ __align__(16) __nv_bfloat16 Ah[128 * AST];
    __shared__ __align__(16) __nv_bfloat16 Al[128 * AST];
    __shared__ __align__(16) __nv_bfloat16 Bh[KC * BST];
    __shared__ __align__(16) __nv_bfloat16 Bl[KC * BST];

    const float* __restrict__ A = (MODE == 1) ? Ain : (const float*)g_hr;
    __half* __restrict__ Out    = (MODE == 1) ? g_h1 : g_h2;
    const __nv_bfloat16* __restrict__ WH = (MODE == 1) ? g_w1h : g_w2h;
    const __nv_bfloat16* __restrict__ WL = (MODE == 1) ? g_w1l : g_w2l;

    const int tid = threadIdx.x, lane = tid & 31, wid = tid >> 5;
    const int warp_m = wid & 3, warp_n = wid >> 2;
    const int rbase = blockIdx.x * 128;

    const uint32_t ah_b = s2u(Ah), al_b = s2u(Al);
    const uint32_t bh_b = s2u(Bh), bl_b = s2u(Bl);

    float acc[2][NT8][4];
    #pragma unroll
    for (int a = 0; a < 2; a++)
        #pragma unroll
        for (int b = 0; b < NT8; b++)
            #pragma unroll
            for (int c = 0; c < 4; c++) acc[a][b][c] = 0.f;

    const int a_row = (lane & 15);
    const int a_col = 8 * (lane >> 4);
    const int b_row = (lane & 15);
    const int b_col = 8 * (lane >> 4);

    const float4* av = (const float4*)A;
    constexpr int ROWF4 = KT / 4;

    for (int ch = 0; ch < KT / KC; ch++) {
        const int c0 = ch * KC;

        // ---- stage A chunk: 128 x 32 fp32 -> bf16 hi/lo ----
        #pragma unroll
        for (int i = 0; i < 4; i++) {
            int idx = tid + i * 256;
            int r = idx >> 3;
            int f = idx & 7;
            float4 v = make_float4(0.f, 0.f, 0.f, 0.f);
            int gr = rbase + r;
            if (gr < NN) v = av[(size_t)gr * ROWF4 + (c0 >> 2) + f];

            __nv_bfloat16 hx = __float2bfloat16(v.x), hy = __float2bfloat16(v.y);
            __nv_bfloat16 hz = __float2bfloat16(v.z), hw = __float2bfloat16(v.w);
            uint2 hp, lp;
            hp.x = pack2(hx, hy);
            hp.y = pack2(hz, hw);
            lp.x = pack2(__float2bfloat16(v.x - __bfloat162float(hx)),
                         __float2bfloat16(v.y - __bfloat162float(hy)));
            lp.y = pack2(__float2bfloat16(v.z - __bfloat162float(hz)),
                         __float2bfloat16(v.w - __bfloat162float(hw)));
            int e = r * AST + f * 4;
            *(uint2*)&Ah[e] = hp;
            *(uint2*)&Al[e] = lp;
        }

        // ---- stage B chunk: 32 x NC bf16 hi/lo ----
        #pragma unroll
        for (int i = 0; i < (KC * NC8) / 256; i++) {
            int idx = tid + i * 256;
            int k = idx / NC8, n8 = idx % NC8;
            int e = k * BST + n8 * 8;
            size_t ge = (size_t)(c0 + k) * NC + n8 * 8;
            *(uint4*)&Bh[e] = *(const uint4*)&WH[ge];
            *(uint4*)&Bl[e] = *(const uint4*)&WL[ge];
        }
        __syncthreads();

        // ---- compute: 2 k16 steps ----
        #pragma unroll
        for (int ks = 0; ks < 2; ks++) {
            const int k16 = ks * 16;
            uint32_t afh[2][4], afl[2][4];
            #pragma unroll
            for (int mi = 0; mi < 2; mi++) {
                uint32_t off = (uint32_t)(((warp_m * 32 + mi * 16 + a_row) * AST
                                           + k16 + a_col) * 2);
                ldsm4(afh[mi], ah_b + off);
                ldsm4(afl[mi], al_b + off);
            }
            #pragma unroll
            for (int ni = 0; ni < NT16; ni++) {
                uint32_t off = (uint32_t)(((k16 + b_row) * BST
                                           + warp_n * NWN + ni * 16 + b_col) * 2);
                uint32_t bfh[4], bfl[4];
                ldsm4t(bfh, bh_b + off);
                ldsm4t(bfl, bl_b + off);
                #pragma unroll
                for (int mi = 0; mi < 2; mi++) {
                    mma16816(acc[mi][2 * ni],     afh[mi], bfh[0], bfh[1]);  // hi*hi
                    mma16816(acc[mi][2 * ni + 1], afh[mi], bfh[2], bfh[3]);
                    mma16816(acc[mi][2 * ni],     afh[mi], bfl[0], bfl[1]);  // hi*lo
                    mma16816(acc[mi][2 * ni + 1], afh[mi], bfl[2], bfl[3]);
                    mma16816(acc[mi][2 * ni],     afl[mi], bfh[0], bfh[1]);  // lo*hi
                    mma16816(acc[mi][2 * ni + 1], afl[mi], bfh[2], bfh[3]);
                }
            }
        }
        __syncthreads();
    }

    // ---- epilogue: fp16 write (c0,c1 contiguous cols -> __half2) ----
    const int g = lane >> 2, tig = lane & 3;
    #pragma unroll
    for (int mi = 0; mi < 2; mi++) {
        int row0 = rbase + warp_m * 32 + mi * 16 + g;
        #pragma unroll
        for (int ni = 0; ni < NT8; ni++) {
            int col = warp_n * NWN + ni * 8 + tig * 2;
            if (row0 < NN)
                *(__half2*)&Out[(size_t)row0 * NC + col] =
                    __floats2half2_rn(acc[mi][ni][0], acc[mi][ni][1]);
            if (row0 + 8 < NN)
                *(__half2*)&Out[(size_t)(row0 + 8) * NC + col] =
                    __floats2half2_rn(acc[mi][ni][2], acc[mi][ni][3]);
        }
    }
}

// ---------------- Layer-1 aggregation (fp16 gather) + bias + ReLU ----------------
// One warp per node; lane owns 4 channels (uint2 = 4 halves).
__global__ void k_agg1(const float* __restrict__ b1) {
    int gw   = (blockIdx.x * blockDim.x + threadIdx.x) >> 5;
    int lane = threadIdx.x & 31;
    if (gw >= NN) return;

    int start = g_rowstart[gw];
    int cnt   = g_deg[gw] - 1;
    float dd  = g_dinv[gw];

    const uint2* h1v = (const uint2*)g_h1;   // 32 uint2 per row (128 halves)
    float4 acc = make_float4(0.f, 0.f, 0.f, 0.f);

    int i = 0;
    for (; i + 1 < cnt; i += 2) {
        int s0 = g_csr[start + i];
        int s1 = g_csr[start + i + 1];
        float c0 = dd * g_dinv[s0];
        float c1 = dd * g_dinv[s1];
        uint2 r0 = h1v[(size_t)s0 * 32 + lane];
        uint2 r1 = h1v[(size_t)s1 * 32 + lane];
        float2 a0 = __half22float2(*(__half2*)&r0.x);
        float2 a1 = __half22float2(*(__half2*)&r0.y);
        float2 b0 = __half22float2(*(__half2*)&r1.x);
        float2 b1_ = __half22float2(*(__half2*)&r1.y);
        acc.x += c0 * a0.x + c1 * b0.x;
        acc.y += c0 * a0.y + c1 * b0.y;
        acc.z += c0 * a1.x + c1 * b1_.x;
        acc.w += c0 * a1.y + c1 * b1_.y;
    }
    if (i < cnt) {
        int s0 = g_csr[start + i];
        float c0 = dd * g_dinv[s0];
        uint2 r0 = h1v[(size_t)s0 * 32 + lane];
        float2 a0 = __half22float2(*(__half2*)&r0.x);
        float2 a1 = __half22float2(*(__half2*)&r0.y);
        acc.x += c0 * a0.x; acc.y += c0 * a0.y;
        acc.z += c0 * a1.x; acc.w += c0 * a1.y;
    }

    float c2 = dd * dd;
    uint2 rs = h1v[(size_t)gw * 32 + lane];
    float2 s0f = __half22float2(*(__half2*)&rs.x);
    float2 s1f = __half22float2(*(__half2*)&rs.y);
    float4 bb = ((const float4*)b1)[lane];
    float4 o;
    o.x = fmaxf(acc.x + c2 * s0f.x + bb.x, 0.f);
    o.y = fmaxf(acc.y + c2 * s0f.y + bb.y, 0.f);
    o.z = fmaxf(acc.z + c2 * s1f.x + bb.z, 0.f);
    o.w = fmaxf(acc.w + c2 * s1f.y + bb.w, 0.f);
    ((float4*)g_hr)[(size_t)gw * 32 + lane] = o;
}

// ---------------- Layer-2 aggregation (fp16 gather) + bias + log_softmax ----------------
// One warp per node; lane owns 2 channels (__half2). Softmax over 64 via shfl.
__global__ void k_agg2(const float* __restrict__ b2, float* __restrict__ out) {
    int gw   = (blockIdx.x * blockDim.x + threadIdx.x) >> 5;
    int lane = threadIdx.x & 31;
    if (gw >= NN) return;

    int start = g_rowstart[gw];
    int cnt   = g_deg[gw] - 1;
    float dd  = g_dinv[gw];

    const __half2* h2v = (const __half2*)g_h2;   // 32 half2 per row
    float2 acc = make_float2(0.f, 0.f);

    int i = 0;
    for (; i + 1 < cnt; i += 2) {
        int s0 = g_csr[start + i];
        int s1 = g_csr[start + i + 1];
        float c0 = dd * g_dinv[s0];
        float c1 = dd * g_dinv[s1];
        float2 v0 = __half22float2(h2v[(size_t)s0 * 32 + lane]);
        float2 v1 = __half22float2(h2v[(size_t)s1 * 32 + lane]);
        acc.x += c0 * v0.x + c1 * v1.x;
        acc.y += c0 * v0.y + c1 * v1.y;
    }
    if (i < cnt) {
        int s0 = g_csr[start + i];
        float c0 = dd * g_dinv[s0];
        float2 v0 = __half22float2(h2v[(size_t)s0 * 32 + lane]);
        acc.x += c0 * v0.x;
        acc.y += c0 * v0.y;
    }

    float c2 = dd * dd;
    float2 hv = __half22float2(h2v[(size_t)gw * 32 + lane]);
    float2 bb = ((const float2*)b2)[lane];
    float a = acc.x + c2 * hv.x + bb.x;
    float b = acc.y + c2 * hv.y + bb.y;

    float m = fmaxf(a, b);
    #pragma unroll
    for (int off = 16; off > 0; off >>= 1)
        m = fmaxf(m, __shfl_xor_sync(0xFFFFFFFFu, m, off));
    float s = expf(a - m) + expf(b - m);
    #pragma unroll
    for (int off = 16; off > 0; off >>= 1)
        s += __shfl_xor_sync(0xFFFFFFFFu, s, off);
    float l = m + logf(s);

    float2 o = make_float2(a - l, b - l);
    ((float2*)out)[(size_t)gw * 32 + lane] = o;
}

// ---------------- launch ----------------
extern "C" void kernel_launch(void* const* d_in, const int* in_sizes, int n_in,
                              void* d_out, int out_size) {
    const float* x   = (const float*)d_in[0];
    const void*  ei  = (const void*)d_in[1];
    const float* W1  = (const float*)d_in[2];
    const float* b1  = (const float*)d_in[3];
    const float* W2  = (const float*)d_in[4];
    const float* b2  = (const float*)d_in[5];
    float*       out = (float*)d_out;

    // edge index: detect int32 vs int64 on-device; convert dst (+degree)
    k_deg_init<<<(NN + 255) / 256, 256>>>();
    k_detect<<<1, 32>>>(ei);
    k_convert<<<(NE + 255) / 256, 256>>>(ei);
    k_dinv<<<(NN + 255) / 256, 256>>>();
    k_wsplit<<<(F0 * F1 + F1 * F2 + 255) / 256, 256>>>(W1, W2);

    // CSR build
    k_scan_partial<<<NBLK_SCAN, 1024>>>();
    k_scan_base<<<1, 128>>>();
    k_scan_write<<<NBLK_SCAN, 1024>>>();
    k_fill<<<(NE + 255) / 256, 256>>>(ei);

    const int NTILE = (NN + 127) / 128;

    // layer 1: split-bf16 tensor-core GEMM + fp16 gather agg (+bias+relu)
    k_mma<F1, F0, 1><<<NTILE, 256>>>(x);
    k_agg1<<<(NN * 32 + 255) / 256, 256>>>(b1);

    // layer 2: GEMM + fp16 gather agg (+bias + fused log_softmax)
    k_mma<F2, F1, 2><<<NTILE, 256>>>(x);
    k_agg2<<<(NN * 32 + 255) / 256, 256>>>(b2, out);
}

// round 9
// speedup vs baseline: 1.2187x; 1.0862x over previous
#include <cuda_runtime.h>
#include <cuda_bf16.h>
#include <cuda_fp16.h>
#include <cstdint>

#define NN 100000
#define NE 1600000
#define F0 256
#define F1 128
#define F2 64
#define NBLK_SCAN 98   // ceil(NN/1024)

// ---- scratch (device globals; no allocation allowed) ----
__device__ __align__(16) __half g_h1[NN * F1];   // x @ W1          (fp16 gather operand)
__device__ float g_hr[NN * F1];                  // relu(agg1+b1)   (fp32: GEMM2 input)
__device__ __align__(16) __half g_h2[NN * F2];   // hr @ W2         (fp16 gather operand)
__device__ float g_dinv[NN];
__device__ int   g_deg[NN];
__device__ int   g_rowstart[NN];
__device__ int   g_cursor[NN];
__device__ int   g_csr[NE];
__device__ int   g_dst[NE];
__device__ int   g_is32;
__device__ int   g_part[128];
__device__ int   g_base[128];
// W split into bf16 hi/lo (row-major [k][n])
__device__ __align__(16) __nv_bfloat16 g_w1h[F0 * F1];
__device__ __align__(16) __nv_bfloat16 g_w1l[F0 * F1];
__device__ __align__(16) __nv_bfloat16 g_w2h[F1 * F2];
__device__ __align__(16) __nv_bfloat16 g_w2l[F1 * F2];

// ================= mma.sync helpers (sm_80+ PTX; safe on base sm_103) =========
__device__ __forceinline__ uint32_t s2u(const void* p) {
    uint32_t a;
    asm("{ .reg .u64 t; cvta.to.shared.u64 t, %1; cvt.u32.u64 %0, t; }" : "=r"(a) : "l"(p));
    return a;
}

__device__ __forceinline__ void ldsm4(uint32_t* r, uint32_t a) {
    asm volatile("ldmatrix.sync.aligned.m8n8.x4.shared.b16 {%0,%1,%2,%3}, [%4];"
                 : "=r"(r[0]), "=r"(r[1]), "=r"(r[2]), "=r"(r[3]) : "r"(a));
}
__device__ __forceinline__ void ldsm4t(uint32_t* r, uint32_t a) {
    asm volatile("ldmatrix.sync.aligned.m8n8.x4.trans.shared.b16 {%0,%1,%2,%3}, [%4];"
                 : "=r"(r[0]), "=r"(r[1]), "=r"(r[2]), "=r"(r[3]) : "r"(a));
}
__device__ __forceinline__ void mma16816(float* c, const uint32_t* a,
                                         uint32_t b0, uint32_t b1) {
    asm volatile("mma.sync.aligned.m16n8k16.row.col.f32.bf16.bf16.f32 "
                 "{%0,%1,%2,%3}, {%4,%5,%6,%7}, {%8,%9}, {%0,%1,%2,%3};"
                 : "+f"(c[0]), "+f"(c[1]), "+f"(c[2]), "+f"(c[3])
                 : "r"(a[0]), "r"(a[1]), "r"(a[2]), "r"(a[3]), "r"(b0), "r"(b1));
}

__device__ __forceinline__ uint32_t pack2(__nv_bfloat16 a, __nv_bfloat16 b) {
    return (uint32_t)__bfloat16_as_ushort(a) | ((uint32_t)__bfloat16_as_ushort(b) << 16);
}

// ---------------- edge dtype detect + dst convert (+fused degree count) ----------------
__global__ void k_detect(const void* __restrict__ ei) {
    if (blockIdx.x == 0 && threadIdx.x == 0) {
        const long long* e64 = (const long long*)ei;
        int ok64 = 1;
        for (int i = 0; i < 128; i++) {
            long long v = e64[i];
            if (v < 0 || v >= NN) { ok64 = 0; break; }
        }
        g_is32 = ok64 ? 0 : 1;
    }
}

__global__ void k_convert(const void* __restrict__ ei) {
    int i = blockIdx.x * blockDim.x + threadIdx.x;
    if (i >= NE) return;
    int v;
    if (g_is32) v = ((const int*)ei)[NE + i];
    else        v = (int)((const long long*)ei)[NE + i];
    g_dst[i] = v;
    if (v >= 0 && v < NN) atomicAdd(&g_deg[v], 1);   // fused degree count
}

__global__ void k_deg_init() {
    int i = blockIdx.x * blockDim.x + threadIdx.x;
    if (i < NN) g_deg[i] = 1;   // +1 self loop baked in
}

__global__ void k_dinv() {
    int i = blockIdx.x * blockDim.x + threadIdx.x;
    if (i < NN) g_dinv[i] = rsqrtf((float)g_deg[i]);
}

// ---------------- W split to bf16 hi/lo ----------------
__global__ void k_wsplit(const float* __restrict__ W1, const float* __restrict__ W2) {
    int i = blockIdx.x * blockDim.x + threadIdx.x;
    if (i < F0 * F1) {
        float v = W1[i];
        __nv_bfloat16 h = __float2bfloat16(v);
        g_w1h[i] = h;
        g_w1l[i] = __float2bfloat16(v - __bfloat162float(h));
    } else if (i < F0 * F1 + F1 * F2) {
        int j = i - F0 * F1;
        float v = W2[j];
        __nv_bfloat16 h = __float2bfloat16(v);
        g_w2h[j] = h;
        g_w2l[j] = __float2bfloat16(v - __bfloat162float(h));
    }
}

// ---------------- CSR build: 3-phase scan of (deg-1), then cursor fill ----------------
__global__ void k_scan_partial() {
    __shared__ int s[1024];
    int t = threadIdx.x;
    int i = blockIdx.x * 1024 + t;
    int v = (i < NN) ? (g_deg[i] - 1) : 0;
    s[t] = v;
    __syncthreads();
    for (int off = 512; off > 0; off >>= 1) {
        if (t < off) s[t] += s[t + off];
        __syncthreads();
    }
    if (t == 0) g_part[blockIdx.x] = s[0];
}

__global__ void k_scan_base() {
    __shared__ int s[128];
    int t = threadIdx.x;
    int v = (t < NBLK_SCAN) ? g_part[t] : 0;
    s[t] = v;
    __syncthreads();
    for (int off = 1; off < 128; off <<= 1) {
        int u = (t >= off) ? s[t - off] : 0;
        __syncthreads();
        s[t] += u;
        __syncthreads();
    }
    if (t < NBLK_SCAN) g_base[t] = s[t] - v;  // exclusive
}

__global__ void k_scan_write() {
    __shared__ int s[1024];
    int t = threadIdx.x;
    int i = blockIdx.x * 1024 + t;
    int v = (i < NN) ? (g_deg[i] - 1) : 0;
    s[t] = v;
    __syncthreads();
    for (int off = 1; off < 1024; off <<= 1) {
        int u = (t >= off) ? s[t - off] : 0;
        __syncthreads();
        s[t] += u;
        __syncthreads();
    }
    if (i < NN) {
        int start = g_base[blockIdx.x] + s[t] - v;
        g_rowstart[i] = start;
        g_cursor[i]   = start;
    }
}

__global__ void k_fill(const void* __restrict__ ei) {
    int i = blockIdx.x * blockDim.x + threadIdx.x;
    if (i < NE) {
        int d = g_dst[i];
        if (d < 0 || d >= NN) return;
        int s;
        if (g_is32) s = ((const int*)ei)[i];
        else        s = (int)((const long long*)ei)[i];
        int pos = atomicAdd(&g_cursor[d], 1);
        if (pos >= 0 && pos < NE) g_csr[pos] = s;
    }
}

// =======================================================================
// Split-bf16 mma.sync GEMM:  Out[M,NC](fp16) = A[M,KT](fp32) @ W[KT,NC]
// fp32 A split to bf16 hi/lo during smem staging; W pre-split in globals.
// 3 MMA passes (hi*hi + hi*lo + lo*hi) give ~fp32 precision.
// CTA: 128 rows x NC cols, 256 threads = 8 warps (4 M x 2 N). K chunk 32.
// MODE 1: A=x,   Out=g_h1, W=g_w1*.   MODE 2: A=g_hr, Out=g_h2, W=g_w2*.
// =======================================================================
template<int NC, int KT, int MODE>
__global__ void __launch_bounds__(256, 2) k_mma(const float* __restrict__ Ain) {
    constexpr int KC   = 32;
    constexpr int AST  = 40;        // bf16 per A smem row (32 + 8 pad)
    constexpr int BST  = NC + 8;
    constexpr int NWN  = NC / 2;
    constexpr int NT8  = NWN / 8;
    constexpr int NT16 = NWN / 16;
    constexpr int NC8  = NC / 8;

    __shared__ __align__(16) __nv_bfloat16 Ah[128 * AST];
    __shared__ __align__(16) __nv_bfloat16 Al[128 * AST];
    __shared__ __align__(16) __nv_bfloat16 Bh[KC * BST];
    __shared__ __align__(16) __nv_bfloat16 Bl[KC * BST];

    const float* __restrict__ A = (MODE == 1) ? Ain : (const float*)g_hr;
    __half* __restrict__ Out    = (MODE == 1) ? g_h1 : g_h2;
    const __nv_bfloat16* __restrict__ WH = (MODE == 1) ? g_w1h : g_w2h;
    const __nv_bfloat16* __restrict__ WL = (MODE == 1) ? g_w1l : g_w2l;

    const int tid = threadIdx.x, lane = tid & 31, wid = tid >> 5;
    const int warp_m = wid & 3, warp_n = wid >> 2;
    const int rbase = blockIdx.x * 128;

    const uint32_t ah_b = s2u(Ah), al_b = s2u(Al);
    const uint32_t bh_b = s2u(Bh), bl_b = s2u(Bl);

    float acc[2][NT8][4];
    #pragma unroll
    for (int a = 0; a < 2; a++)
        #pragma unroll
        for (int b = 0; b < NT8; b++)
            #pragma unroll
            for (int c = 0; c < 4; c++) acc[a][b][c] = 0.f;

    const int a_row = (lane & 15);
    const int a_col = 8 * (lane >> 4);
    const int b_row = (lane & 15);
    const int b_col = 8 * (lane >> 4);

    const float4* av = (const float4*)A;
    constexpr int ROWF4 = KT / 4;

    for (int ch = 0; ch < KT / KC; ch++) {
        const int c0 = ch * KC;

        // ---- stage A chunk: 128 x 32 fp32 -> bf16 hi/lo ----
        #pragma unroll
        for (int i = 0; i < 4; i++) {
            int idx = tid + i * 256;
            int r = idx >> 3;
            int f = idx & 7;
            float4 v = make_float4(0.f, 0.f, 0.f, 0.f);
            int gr = rbase + r;
            if (gr < NN) v = av[(size_t)gr * ROWF4 + (c0 >> 2) + f];

            __nv_bfloat16 hx = __float2bfloat16(v.x), hy = __float2bfloat16(v.y);
            __nv_bfloat16 hz = __float2bfloat16(v.z), hw = __float2bfloat16(v.w);
            uint2 hp, lp;
            hp.x = pack2(hx, hy);
            hp.y = pack2(hz, hw);
            lp.x = pack2(__float2bfloat16(v.x - __bfloat162float(hx)),
                         __float2bfloat16(v.y - __bfloat162float(hy)));
            lp.y = pack2(__float2bfloat16(v.z - __bfloat162float(hz)),
                         __float2bfloat16(v.w - __bfloat162float(hw)));
            int e = r * AST + f * 4;
            *(uint2*)&Ah[e] = hp;
            *(uint2*)&Al[e] = lp;
        }

        // ---- stage B chunk: 32 x NC bf16 hi/lo ----
        #pragma unroll
        for (int i = 0; i < (KC * NC8) / 256; i++) {
            int idx = tid + i * 256;
            int k = idx / NC8, n8 = idx % NC8;
            int e = k * BST + n8 * 8;
            size_t ge = (size_t)(c0 + k) * NC + n8 * 8;
            *(uint4*)&Bh[e] = *(const uint4*)&WH[ge];
            *(uint4*)&Bl[e] = *(const uint4*)&WL[ge];
        }
        __syncthreads();

        // ---- compute: 2 k16 steps ----
        #pragma unroll
        for (int ks = 0; ks < 2; ks++) {
            const int k16 = ks * 16;
            uint32_t afh[2][4], afl[2][4];
            #pragma unroll
            for (int mi = 0; mi < 2; mi++) {
                uint32_t off = (uint32_t)(((warp_m * 32 + mi * 16 + a_row) * AST
                                           + k16 + a_col) * 2);
                ldsm4(afh[mi], ah_b + off);
                ldsm4(afl[mi], al_b + off);
            }
            #pragma unroll
            for (int ni = 0; ni < NT16; ni++) {
                uint32_t off = (uint32_t)(((k16 + b_row) * BST
                                           + warp_n * NWN + ni * 16 + b_col) * 2);
                uint32_t bfh[4], bfl[4];
                ldsm4t(bfh, bh_b + off);
                ldsm4t(bfl, bl_b + off);
                #pragma unroll
                for (int mi = 0; mi < 2; mi++) {
                    mma16816(acc[mi][2 * ni],     afh[mi], bfh[0], bfh[1]);  // hi*hi
                    mma16816(acc[mi][2 * ni + 1], afh[mi], bfh[2], bfh[3]);
                    mma16816(acc[mi][2 * ni],     afh[mi], bfl[0], bfl[1]);  // hi*lo
                    mma16816(acc[mi][2 * ni + 1], afh[mi], bfl[2], bfl[3]);
                    mma16816(acc[mi][2 * ni],     afl[mi], bfh[0], bfh[1]);  // lo*hi
                    mma16816(acc[mi][2 * ni + 1], afl[mi], bfh[2], bfh[3]);
                }
            }
        }
        __syncthreads();
    }

    // ---- epilogue: fp16 write (c0,c1 contiguous cols -> __half2) ----
    const int g = lane >> 2, tig = lane & 3;
    #pragma unroll
    for (int mi = 0; mi < 2; mi++) {
        int row0 = rbase + warp_m * 32 + mi * 16 + g;
        #pragma unroll
        for (int ni = 0; ni < NT8; ni++) {
            int col = warp_n * NWN + ni * 8 + tig * 2;
            if (row0 < NN)
                *(__half2*)&Out[(size_t)row0 * NC + col] =
                    __floats2half2_rn(acc[mi][ni][0], acc[mi][ni][1]);
            if (row0 + 8 < NN)
                *(__half2*)&Out[(size_t)(row0 + 8) * NC + col] =
                    __floats2half2_rn(acc[mi][ni][2], acc[mi][ni][3]);
        }
    }
}

// ---------------- Layer-1 aggregation (fp16 gather) + bias + ReLU ----------------
// One warp per node; lane owns 4 channels (uint2 = 4 halves).
__global__ void k_agg1(const float* __restrict__ b1) {
    int gw   = (blockIdx.x * blockDim.x + threadIdx.x) >> 5;
    int lane = threadIdx.x & 31;
    if (gw >= NN) return;

    int start = g_rowstart[gw];
    int cnt   = g_deg[gw] - 1;
    float dd  = g_dinv[gw];

    const uint2* h1v = (const uint2*)g_h1;   // 32 uint2 per row (128 halves)
    float4 acc = make_float4(0.f, 0.f, 0.f, 0.f);

    int i = 0;
    for (; i + 1 < cnt; i += 2) {
        int s0 = g_csr[start + i];
        int s1 = g_csr[start + i + 1];
        float c0 = dd * g_dinv[s0];
        float c1 = dd * g_dinv[s1];
        uint2 r0 = h1v[(size_t)s0 * 32 + lane];
        uint2 r1 = h1v[(size_t)s1 * 32 + lane];
        float2 a0 = __half22float2(*(__half2*)&r0.x);
        float2 a1 = __half22float2(*(__half2*)&r0.y);
        float2 b0 = __half22float2(*(__half2*)&r1.x);
        float2 b1_ = __half22float2(*(__half2*)&r1.y);
        acc.x += c0 * a0.x + c1 * b0.x;
        acc.y += c0 * a0.y + c1 * b0.y;
        acc.z += c0 * a1.x + c1 * b1_.x;
        acc.w += c0 * a1.y + c1 * b1_.y;
    }
    if (i < cnt) {
        int s0 = g_csr[start + i];
        float c0 = dd * g_dinv[s0];
        uint2 r0 = h1v[(size_t)s0 * 32 + lane];
        float2 a0 = __half22float2(*(__half2*)&r0.x);
        float2 a1 = __half22float2(*(__half2*)&r0.y);
        acc.x += c0 * a0.x; acc.y += c0 * a0.y;
        acc.z += c0 * a1.x; acc.w += c0 * a1.y;
    }

    float c2 = dd * dd;
    uint2 rs = h1v[(size_t)gw * 32 + lane];
    float2 s0f = __half22float2(*(__half2*)&rs.x);
    float2 s1f = __half22float2(*(__half2*)&rs.y);
    float4 bb = ((const float4*)b1)[lane];
    float4 o;
    o.x = fmaxf(acc.x + c2 * s0f.x + bb.x, 0.f);
    o.y = fmaxf(acc.y + c2 * s0f.y + bb.y, 0.f);
    o.z = fmaxf(acc.z + c2 * s1f.x + bb.z, 0.f);
    o.w = fmaxf(acc.w + c2 * s1f.y + bb.w, 0.f);
    ((float4*)g_hr)[(size_t)gw * 32 + lane] = o;
}

// ---------------- Layer-2 aggregation (fp16 gather) + bias + log_softmax ----------------
// One warp per node; lane owns 2 channels (__half2). Softmax over 64 via shfl.
__global__ void k_agg2(const float* __restrict__ b2, float* __restrict__ out) {
    int gw   = (blockIdx.x * blockDim.x + threadIdx.x) >> 5;
    int lane = threadIdx.x & 31;
    if (gw >= NN) return;

    int start = g_rowstart[gw];
    int cnt   = g_deg[gw] - 1;
    float dd  = g_dinv[gw];

    const __half2* h2v = (const __half2*)g_h2;   // 32 half2 per row
    float2 acc = make_float2(0.f, 0.f);

    int i = 0;
    for (; i + 1 < cnt; i += 2) {
        int s0 = g_csr[start + i];
        int s1 = g_csr[start + i + 1];
        float c0 = dd * g_dinv[s0];
        float c1 = dd * g_dinv[s1];
        float2 v0 = __half22float2(h2v[(size_t)s0 * 32 + lane]);
        float2 v1 = __half22float2(h2v[(size_t)s1 * 32 + lane]);
        acc.x += c0 * v0.x + c1 * v1.x;
        acc.y += c0 * v0.y + c1 * v1.y;
    }
    if (i < cnt) {
        int s0 = g_csr[start + i];
        float c0 = dd * g_dinv[s0];
        float2 v0 = __half22float2(h2v[(size_t)s0 * 32 + lane]);
        acc.x += c0 * v0.x;
        acc.y += c0 * v0.y;
    }

    float c2 = dd * dd;
    float2 hv = __half22float2(h2v[(size_t)gw * 32 + lane]);
    float2 bb = ((const float2*)b2)[lane];
    float a = acc.x + c2 * hv.x + bb.x;
    float b = acc.y + c2 * hv.y + bb.y;

    float m = fmaxf(a, b);
    #pragma unroll
    for (int off = 16; off > 0; off >>= 1)
        m = fmaxf(m, __shfl_xor_sync(0xFFFFFFFFu, m, off));
    float s = expf(a - m) + expf(b - m);
    #pragma unroll
    for (int off = 16; off > 0; off >>= 1)
        s += __shfl_xor_sync(0xFFFFFFFFu, s, off);
    float l = m + logf(s);

    float2 o = make_float2(a - l, b - l);
    ((float2*)out)[(size_t)gw * 32 + lane] = o;
}

// ---------------- launch ----------------
// The CSR-build chain (side stream) is independent of wsplit+GEMM1 (main
// stream); fork/join with events so both are captured into one graph and
// overlap. Streams/events created lazily once (host-side only; identical
// work on every call).
extern "C" void kernel_launch(void* const* d_in, const int* in_sizes, int n_in,
                              void* d_out, int out_size) {
    const float* x   = (const float*)d_in[0];
    const void*  ei  = (const void*)d_in[1];
    const float* W1  = (const float*)d_in[2];
    const float* b1  = (const float*)d_in[3];
    const float* W2  = (const float*)d_in[4];
    const float* b2  = (const float*)d_in[5];
    float*       out = (float*)d_out;

    static cudaStream_t s_side = nullptr;
    static cudaEvent_t  ev_fork = nullptr, ev_join = nullptr;
    if (s_side == nullptr) {
        cudaStreamCreateWithFlags(&s_side, cudaStreamNonBlocking);
        cudaEventCreateWithFlags(&ev_fork, cudaEventDisableTiming);
        cudaEventCreateWithFlags(&ev_join, cudaEventDisableTiming);
    }

    // ---- fork: CSR chain on side stream ----
    cudaEventRecord(ev_fork, 0);
    cudaStreamWaitEvent(s_side, ev_fork, 0);
    k_deg_init<<<(NN + 255) / 256, 256, 0, s_side>>>();
    k_detect<<<1, 32, 0, s_side>>>(ei);
    k_convert<<<(NE + 255) / 256, 256, 0, s_side>>>(ei);
    k_dinv<<<(NN + 255) / 256, 256, 0, s_side>>>();
    k_scan_partial<<<NBLK_SCAN, 1024, 0, s_side>>>();
    k_scan_base<<<1, 128, 0, s_side>>>();
    k_scan_write<<<NBLK_SCAN, 1024, 0, s_side>>>();
    k_fill<<<(NE + 255) / 256, 256, 0, s_side>>>(ei);
    cudaEventRecord(ev_join, s_side);

    // ---- main stream: weight split + layer-1 GEMM (independent of CSR) ----
    k_wsplit<<<(F0 * F1 + F1 * F2 + 255) / 256, 256>>>(W1, W2);
    const int NTILE = (NN + 127) / 128;
    k_mma<F1, F0, 1><<<NTILE, 256>>>(x);

    // ---- join, then the dependent tail ----
    cudaStreamWaitEvent(0, ev_join, 0);
    k_agg1<<<(NN * 32 + 255) / 256, 256>>>(b1);
    k_mma<F2, F1, 2><<<NTILE, 256>>>(x);
    k_agg2<<<(NN * 32 + 255) / 256, 256>>>(b2, out);
}

// round 10
// speedup vs baseline: 1.2856x; 1.0549x over previous
#include <cuda_runtime.h>
#include <cuda_bf16.h>
#include <cuda_fp16.h>
#include <cstdint>

#define NN 100000
#define NE 1600000
#define F0 256
#define F1 128
#define F2 64
#define NBLK_SCAN 98   // ceil(NN/1024)

// ---- scratch (device globals; no allocation allowed) ----
__device__ __align__(16) __half g_h1[NN * F1];   // x @ W1          (fp16 gather operand)
__device__ __align__(16) __half g_hr[NN * F1];   // relu(agg1+b1)   (fp16: GEMM2 A input)
__device__ __align__(16) __half g_h2[NN * F2];   // hr @ W2         (fp16 gather operand)
__device__ float g_dinv[NN];
__device__ int   g_deg[NN];
__device__ int   g_rowstart[NN];
__device__ int   g_cursor[NN];
__device__ int   g_csr[NE];
__device__ int   g_dst[NE];
__device__ int   g_is32;
__device__ int   g_part[128];
__device__ int   g_base[128];
// W1 split into bf16 hi/lo (row-major [k][n]); W2 split into fp16 hi/lo
__device__ __align__(16) __nv_bfloat16 g_w1h[F0 * F1];
__device__ __align__(16) __nv_bfloat16 g_w1l[F0 * F1];
__device__ __align__(16) __half        g_w2h[F1 * F2];
__device__ __align__(16) __half        g_w2l[F1 * F2];

// ================= mma.sync helpers (sm_80+ PTX; safe on base sm_103) =========
__device__ __forceinline__ uint32_t s2u(const void* p) {
    uint32_t a;
    asm("{ .reg .u64 t; cvta.to.shared.u64 t, %1; cvt.u32.u64 %0, t; }" : "=r"(a) : "l"(p));
    return a;
}

__device__ __forceinline__ void ldsm4(uint32_t* r, uint32_t a) {
    asm volatile("ldmatrix.sync.aligned.m8n8.x4.shared.b16 {%0,%1,%2,%3}, [%4];"
                 : "=r"(r[0]), "=r"(r[1]), "=r"(r[2]), "=r"(r[3]) : "r"(a));
}
__device__ __forceinline__ void ldsm4t(uint32_t* r, uint32_t a) {
    asm volatile("ldmatrix.sync.aligned.m8n8.x4.trans.shared.b16 {%0,%1,%2,%3}, [%4];"
                 : "=r"(r[0]), "=r"(r[1]), "=r"(r[2]), "=r"(r[3]) : "r"(a));
}
__device__ __forceinline__ void mma16816(float* c, const uint32_t* a,
                                         uint32_t b0, uint32_t b1) {
    asm volatile("mma.sync.aligned.m16n8k16.row.col.f32.bf16.bf16.f32 "
                 "{%0,%1,%2,%3}, {%4,%5,%6,%7}, {%8,%9}, {%0,%1,%2,%3};"
                 : "+f"(c[0]), "+f"(c[1]), "+f"(c[2]), "+f"(c[3])
                 : "r"(a[0]), "r"(a[1]), "r"(a[2]), "r"(a[3]), "r"(b0), "r"(b1));
}
__device__ __forceinline__ void mma16816h(float* c, const uint32_t* a,
                                          uint32_t b0, uint32_t b1) {
    asm volatile("mma.sync.aligned.m16n8k16.row.col.f32.f16.f16.f32 "
                 "{%0,%1,%2,%3}, {%4,%5,%6,%7}, {%8,%9}, {%0,%1,%2,%3};"
                 : "+f"(c[0]), "+f"(c[1]), "+f"(c[2]), "+f"(c[3])
                 : "r"(a[0]), "r"(a[1]), "r"(a[2]), "r"(a[3]), "r"(b0), "r"(b1));
}

__device__ __forceinline__ uint32_t pack2(__nv_bfloat16 a, __nv_bfloat16 b) {
    return (uint32_t)__bfloat16_as_ushort(a) | ((uint32_t)__bfloat16_as_ushort(b) << 16);
}

// -------- combined degree init + edge dtype detect --------
__global__ void k_deg_init_detect(const void* __restrict__ ei) {
    int i = blockIdx.x * blockDim.x + threadIdx.x;
    if (i < NN) g_deg[i] = 1;   // +1 self loop baked in
    if (i == 0) {
        const long long* e64 = (const long long*)ei;
        int ok64 = 1;
        for (int j = 0; j < 128; j++) {
            long long v = e64[j];
            if (v < 0 || v >= NN) { ok64 = 0; break; }
        }
        g_is32 = ok64 ? 0 : 1;
    }
}

__global__ void k_convert(const void* __restrict__ ei) {
    int i = blockIdx.x * blockDim.x + threadIdx.x;
    if (i >= NE) return;
    int v;
    if (g_is32) v = ((const int*)ei)[NE + i];
    else        v = (int)((const long long*)ei)[NE + i];
    g_dst[i] = v;
    if (v >= 0 && v < NN) atomicAdd(&g_deg[v], 1);   // fused degree count
}

__global__ void k_dinv() {
    int i = blockIdx.x * blockDim.x + threadIdx.x;
    if (i < NN) g_dinv[i] = rsqrtf((float)g_deg[i]);
}

// ---------------- W split: W1 -> bf16 hi/lo, W2 -> fp16 hi/lo ----------------
__global__ void k_wsplit(const float* __restrict__ W1, const float* __restrict__ W2) {
    int i = blockIdx.x * blockDim.x + threadIdx.x;
    if (i < F0 * F1) {
        float v = W1[i];
        __nv_bfloat16 h = __float2bfloat16(v);
        g_w1h[i] = h;
        g_w1l[i] = __float2bfloat16(v - __bfloat162float(h));
    } else if (i < F0 * F1 + F1 * F2) {
        int j = i - F0 * F1;
        float v = W2[j];
        __half h = __float2half_rn(v);
        g_w2h[j] = h;
        g_w2l[j] = __float2half_rn(v - __half2float(h));
    }
}

// ---------------- CSR build: 3-phase scan of (deg-1), then cursor fill ----------------
__global__ void k_scan_partial() {
    __shared__ int s[1024];
    int t = threadIdx.x;
    int i = blockIdx.x * 1024 + t;
    int v = (i < NN) ? (g_deg[i] - 1) : 0;
    s[t] = v;
    __syncthreads();
    for (int off = 512; off > 0; off >>= 1) {
        if (t < off) s[t] += s[t + off];
        __syncthreads();
    }
    if (t == 0) g_part[blockIdx.x] = s[0];
}

__global__ void k_scan_base() {
    __shared__ int s[128];
    int t = threadIdx.x;
    int v = (t < NBLK_SCAN) ? g_part[t] : 0;
    s[t] = v;
    __syncthreads();
    for (int off = 1; off < 128; off <<= 1) {
        int u = (t >= off) ? s[t - off] : 0;
        __syncthreads();
        s[t] += u;
        __syncthreads();
    }
    if (t < NBLK_SCAN) g_base[t] = s[t] - v;  // exclusive
}

__global__ void k_scan_write() {
    __shared__ int s[1024];
    int t = threadIdx.x;
    int i = blockIdx.x * 1024 + t;
    int v = (i < NN) ? (g_deg[i] - 1) : 0;
    s[t] = v;
    __syncthreads();
    for (int off = 1; off < 1024; off <<= 1) {
        int u = (t >= off) ? s[t - off] : 0;
        __syncthreads();
        s[t] += u;
        __syncthreads();
    }
    if (i < NN) {
        int start = g_base[blockIdx.x] + s[t] - v;
        g_rowstart[i] = start;
        g_cursor[i]   = start;
    }
}

__global__ void k_fill(const void* __restrict__ ei) {
    int i = blockIdx.x * blockDim.x + threadIdx.x;
    if (i < NE) {
        int d = g_dst[i];
        if (d < 0 || d >= NN) return;
        int s;
        if (g_is32) s = ((const int*)ei)[i];
        else        s = (int)((const long long*)ei)[i];
        int pos = atomicAdd(&g_cursor[d], 1);
        if (pos >= 0 && pos < NE) g_csr[pos] = s;
    }
}

// =======================================================================
// GEMM1 (split-bf16, 3-pass): g_h1[M,128](fp16) = x[M,256](fp32) @ W1
// CTA: 128 rows x 128 cols, 256 threads = 8 warps (4 M x 2 N). K chunk 32.
// =======================================================================
__global__ void __launch_bounds__(256, 2) k_mma1(const float* __restrict__ Ain) {
    constexpr int NC = F1, KT = F0;
    constexpr int KC   = 32;
    constexpr int AST  = 40;
    constexpr int BST  = NC + 8;
    constexpr int NWN  = NC / 2;
    constexpr int NT8  = NWN / 8;
    constexpr int NT16 = NWN / 16;
    constexpr int NC8  = NC / 8;

    __shared__ __align__(16) __nv_bfloat16 Ah[128 * AST];
    __shared__ __align__(16) __nv_bfloat16 Al[128 * AST];
    __shared__ __align__(16) __nv_bfloat16 Bh[KC * BST];
    __shared__ __align__(16) __nv_bfloat16 Bl[KC * BST];

    const int tid = threadIdx.x, lane = tid & 31, wid = tid >> 5;
    const int warp_m = wid & 3, warp_n = wid >> 2;
    const int rbase = blockIdx.x * 128;

    const uint32_t ah_b = s2u(Ah), al_b = s2u(Al);
    const uint32_t bh_b = s2u(Bh), bl_b = s2u(Bl);

    float acc[2][NT8][4];
    #pragma unroll
    for (int a = 0; a < 2; a++)
        #pragma unroll
        for (int b = 0; b < NT8; b++)
            #pragma unroll
            for (int c = 0; c < 4; c++) acc[a][b][c] = 0.f;

    const int a_row = (lane & 15);
    const int a_col = 8 * (lane >> 4);
    const int b_row = (lane & 15);
    const int b_col = 8 * (lane >> 4);

    const float4* av = (const float4*)Ain;
    constexpr int ROWF4 = KT / 4;

    for (int ch = 0; ch < KT / KC; ch++) {
        const int c0 = ch * KC;

        #pragma unroll
        for (int i = 0; i < 4; i++) {
            int idx = tid + i * 256;
            int r = idx >> 3;
            int f = idx & 7;
            float4 v = make_float4(0.f, 0.f, 0.f, 0.f);
            int gr = rbase + r;
            if (gr < NN) v = av[(size_t)gr * ROWF4 + (c0 >> 2) + f];

            __nv_bfloat16 hx = __float2bfloat16(v.x), hy = __float2bfloat16(v.y);
            __nv_bfloat16 hz = __float2bfloat16(v.z), hw = __float2bfloat16(v.w);
            uint2 hp, lp;
            hp.x = pack2(hx, hy);
            hp.y = pack2(hz, hw);
            lp.x = pack2(__float2bfloat16(v.x - __bfloat162float(hx)),
                         __float2bfloat16(v.y - __bfloat162float(hy)));
            lp.y = pack2(__float2bfloat16(v.z - __bfloat162float(hz)),
                         __float2bfloat16(v.w - __bfloat162float(hw)));
            int e = r * AST + f * 4;
            *(uint2*)&Ah[e] = hp;
            *(uint2*)&Al[e] = lp;
        }

        #pragma unroll
        for (int i = 0; i < (KC * NC8) / 256; i++) {
            int idx = tid + i * 256;
            int k = idx / NC8, n8 = idx % NC8;
            int e = k * BST + n8 * 8;
            size_t ge = (size_t)(c0 + k) * NC + n8 * 8;
            *(uint4*)&Bh[e] = *(const uint4*)&g_w1h[ge];
            *(uint4*)&Bl[e] = *(const uint4*)&g_w1l[ge];
        }
        __syncthreads();

        #pragma unroll
        for (int ks = 0; ks < 2; ks++) {
            const int k16 = ks * 16;
            uint32_t afh[2][4], afl[2][4];
            #pragma unroll
            for (int mi = 0; mi < 2; mi++) {
                uint32_t off = (uint32_t)(((warp_m * 32 + mi * 16 + a_row) * AST
                                           + k16 + a_col) * 2);
                ldsm4(afh[mi], ah_b + off);
                ldsm4(afl[mi], al_b + off);
            }
            #pragma unroll
            for (int ni = 0; ni < NT16; ni++) {
                uint32_t off = (uint32_t)(((k16 + b_row) * BST
                                           + warp_n * NWN + ni * 16 + b_col) * 2);
                uint32_t bfh[4], bfl[4];
                ldsm4t(bfh, bh_b + off);
                ldsm4t(bfl, bl_b + off);
                #pragma unroll
                for (int mi = 0; mi < 2; mi++) {
                    mma16816(acc[mi][2 * ni],     afh[mi], bfh[0], bfh[1]);  // hi*hi
                    mma16816(acc[mi][2 * ni + 1], afh[mi], bfh[2], bfh[3]);
                    mma16816(acc[mi][2 * ni],     afh[mi], bfl[0], bfl[1]);  // hi*lo
                    mma16816(acc[mi][2 * ni + 1], afh[mi], bfl[2], bfl[3]);
                    mma16816(acc[mi][2 * ni],     afl[mi], bfh[0], bfh[1]);  // lo*hi
                    mma16816(acc[mi][2 * ni + 1], afl[mi], bfh[2], bfh[3]);
                }
            }
        }
        __syncthreads();
    }

    const int g = lane >> 2, tig = lane & 3;
    #pragma unroll
    for (int mi = 0; mi < 2; mi++) {
        int row0 = rbase + warp_m * 32 + mi * 16 + g;
        #pragma unroll
        for (int ni = 0; ni < NT8; ni++) {
            int col = warp_n * NWN + ni * 8 + tig * 2;
            if (row0 < NN)
                *(__half2*)&g_h1[(size_t)row0 * NC + col] =
                    __floats2half2_rn(acc[mi][ni][0], acc[mi][ni][1]);
            if (row0 + 8 < NN)
                *(__half2*)&g_h1[(size_t)(row0 + 8) * NC + col] =
                    __floats2half2_rn(acc[mi][ni][2], acc[mi][ni][3]);
        }
    }
}

// =======================================================================
// GEMM2 (fp16 A exact, W2 split fp16 hi/lo, 2-pass):
//   g_h2[M,64](fp16) = g_hr[M,128](fp16) @ W2
// CTA: 128 rows x 64 cols, 256 threads = 8 warps (4 M x 2 N). K chunk 32.
// =======================================================================
__global__ void __launch_bounds__(256, 2) k_mma2() {
    constexpr int NC = F2, KT = F1;
    constexpr int KC   = 32;
    constexpr int AST  = 40;
    constexpr int BST  = NC + 8;     // 72
    constexpr int NWN  = NC / 2;     // 32
    constexpr int NT8  = NWN / 8;    // 4
    constexpr int NT16 = NWN / 16;   // 2
    constexpr int NC4  = NC / 4;     // uint2 per B row (16)

    __shared__ __align__(16) __half Ax[128 * AST];
    __shared__ __align__(16) __half Bh[KC * BST];
    __shared__ __align__(16) __half Bl[KC * BST];

    const int tid = threadIdx.x, lane = tid & 31, wid = tid >> 5;
    const int warp_m = wid & 3, warp_n = wid >> 2;
    const int rbase = blockIdx.x * 128;

    const uint32_t ax_b = s2u(Ax);
    const uint32_t bh_b = s2u(Bh), bl_b = s2u(Bl);

    float acc[2][NT8][4];
    #pragma unroll
    for (int a = 0; a < 2; a++)
        #pragma unroll
        for (int b = 0; b < NT8; b++)
            #pragma unroll
            for (int c = 0; c < 4; c++) acc[a][b][c] = 0.f;

    const int a_row = (lane & 15);
    const int a_col = 8 * (lane >> 4);
    const int b_row = (lane & 15);
    const int b_col = 8 * (lane >> 4);

    for (int ch = 0; ch < KT / KC; ch++) {
        const int c0 = ch * KC;

        // ---- stage A chunk: 128 x 32 fp16, direct copy (uint2 = 4 halves) ----
        #pragma unroll
        for (int i = 0; i < 4; i++) {
            int idx = tid + i * 256;            // 0..1023
            int r = idx >> 3;
            int q = idx & 7;                    // uint2 within chunk
            uint2 v = make_uint2(0u, 0u);
            int gr = rbase + r;
            if (gr < NN) v = *(const uint2*)&g_hr[(size_t)gr * KT + c0 + q * 4];
            *(uint2*)&Ax[r * AST + q * 4] = v;
        }

        // ---- stage B chunk: 32 x 64 fp16 hi/lo (uint2) ----
        #pragma unroll
        for (int i = 0; i < (KC * NC4) / 256; i++) {
            int idx = tid + i * 256;
            int k = idx / NC4, n4 = idx % NC4;
            int e = k * BST + n4 * 4;
            size_t ge = (size_t)(c0 + k) * NC + n4 * 4;
            *(uint2*)&Bh[e] = *(const uint2*)&g_w2h[ge];
            *(uint2*)&Bl[e] = *(const uint2*)&g_w2l[ge];
        }
        __syncthreads();

        #pragma unroll
        for (int ks = 0; ks < 2; ks++) {
            const int k16 = ks * 16;
            uint32_t af[2][4];
            #pragma unroll
            for (int mi = 0; mi < 2; mi++) {
                uint32_t off = (uint32_t)(((warp_m * 32 + mi * 16 + a_row) * AST
                                           + k16 + a_col) * 2);
                ldsm4(af[mi], ax_b + off);
            }
            #pragma unroll
            for (int ni = 0; ni < NT16; ni++) {
                uint32_t off = (uint32_t)(((k16 + b_row) * BST
                                           + warp_n * NWN + ni * 16 + b_col) * 2);
                uint32_t bfh[4], bfl[4];
                ldsm4t(bfh, bh_b + off);
                ldsm4t(bfl, bl_b + off);
                #pragma unroll
                for (int mi = 0; mi < 2; mi++) {
                    mma16816h(acc[mi][2 * ni],     af[mi], bfh[0], bfh[1]);  // A*hi
                    mma16816h(acc[mi][2 * ni + 1], af[mi], bfh[2], bfh[3]);
                    mma16816h(acc[mi][2 * ni],     af[mi], bfl[0], bfl[1]);  // A*lo
                    mma16816h(acc[mi][2 * ni + 1], af[mi], bfl[2], bfl[3]);
                }
            }
        }
        __syncthreads();
    }

    const int g = lane >> 2, tig = lane & 3;
    #pragma unroll
    for (int mi = 0; mi < 2; mi++) {
        int row0 = rbase + warp_m * 32 + mi * 16 + g;
        #pragma unroll
        for (int ni = 0; ni < NT8; ni++) {
            int col = warp_n * NWN + ni * 8 + tig * 2;
            if (row0 < NN)
                *(__half2*)&g_h2[(size_t)row0 * NC + col] =
                    __floats2half2_rn(acc[mi][ni][0], acc[mi][ni][1]);
            if (row0 + 8 < NN)
                *(__half2*)&g_h2[(size_t)(row0 + 8) * NC + col] =
                    __floats2half2_rn(acc[mi][ni][2], acc[mi][ni][3]);
        }
    }
}

// ---------------- Layer-1 aggregation (fp16 gather) + bias + ReLU -> fp16 ----------------
__global__ void k_agg1(const float* __restrict__ b1) {
    int gw   = (blockIdx.x * blockDim.x + threadIdx.x) >> 5;
    int lane = threadIdx.x & 31;
    if (gw >= NN) return;

    int start = g_rowstart[gw];
    int cnt   = g_deg[gw] - 1;
    float dd  = g_dinv[gw];

    const uint2* h1v = (const uint2*)g_h1;   // 32 uint2 per row (128 halves)
    float4 acc = make_float4(0.f, 0.f, 0.f, 0.f);

    int i = 0;
    for (; i + 1 < cnt; i += 2) {
        int s0 = g_csr[start + i];
        int s1 = g_csr[start + i + 1];
        float c0 = dd * g_dinv[s0];
        float c1 = dd * g_dinv[s1];
        uint2 r0 = h1v[(size_t)s0 * 32 + lane];
        uint2 r1 = h1v[(size_t)s1 * 32 + lane];
        float2 a0 = __half22float2(*(__half2*)&r0.x);
        float2 a1 = __half22float2(*(__half2*)&r0.y);
        float2 b0 = __half22float2(*(__half2*)&r1.x);
        float2 b1_ = __half22float2(*(__half2*)&r1.y);
        acc.x += c0 * a0.x + c1 * b0.x;
        acc.y += c0 * a0.y + c1 * b0.y;
        acc.z += c0 * a1.x + c1 * b1_.x;
        acc.w += c0 * a1.y + c1 * b1_.y;
    }
    if (i < cnt) {
        int s0 = g_csr[start + i];
        float c0 = dd * g_dinv[s0];
        uint2 r0 = h1v[(size_t)s0 * 32 + lane];
        float2 a0 = __half22float2(*(__half2*)&r0.x);
        float2 a1 = __half22float2(*(__half2*)&r0.y);
        acc.x += c0 * a0.x; acc.y += c0 * a0.y;
        acc.z += c0 * a1.x; acc.w += c0 * a1.y;
    }

    float c2 = dd * dd;
    uint2 rs = h1v[(size_t)gw * 32 + lane];
    float2 s0f = __half22float2(*(__half2*)&rs.x);
    float2 s1f = __half22float2(*(__half2*)&rs.y);
    float4 bb = ((const float4*)b1)[lane];
    float ox = fmaxf(acc.x + c2 * s0f.x + bb.x, 0.f);
    float oy = fmaxf(acc.y + c2 * s0f.y + bb.y, 0.f);
    float oz = fmaxf(acc.z + c2 * s1f.x + bb.z, 0.f);
    float ow = fmaxf(acc.w + c2 * s1f.y + bb.w, 0.f);

    uint2 ov;
    *(__half2*)&ov.x = __floats2half2_rn(ox, oy);
    *(__half2*)&ov.y = __floats2half2_rn(oz, ow);
    ((uint2*)g_hr)[(size_t)gw * 32 + lane] = ov;
}

// ---------------- Layer-2 aggregation (fp16 gather) + bias + log_softmax ----------------
__global__ void k_agg2(const float* __restrict__ b2, float* __restrict__ out) {
    int gw   = (blockIdx.x * blockDim.x + threadIdx.x) >> 5;
    int lane = threadIdx.x & 31;
    if (gw >= NN) return;

    int start = g_rowstart[gw];
    int cnt   = g_deg[gw] - 1;
    float dd  = g_dinv[gw];

    const __half2* h2v = (const __half2*)g_h2;   // 32 half2 per row
    float2 acc = make_float2(0.f, 0.f);

    int i = 0;
    for (; i + 1 < cnt; i += 2) {
        int s0 = g_csr[start + i];
        int s1 = g_csr[start + i + 1];
        float c0 = dd * g_dinv[s0];
        float c1 = dd * g_dinv[s1];
        float2 v0 = __half22float2(h2v[(size_t)s0 * 32 + lane]);
        float2 v1 = __half22float2(h2v[(size_t)s1 * 32 + lane]);
        acc.x += c0 * v0.x + c1 * v1.x;
        acc.y += c0 * v0.y + c1 * v1.y;
    }
    if (i < cnt) {
        int s0 = g_csr[start + i];
        float c0 = dd * g_dinv[s0];
        float2 v0 = __half22float2(h2v[(size_t)s0 * 32 + lane]);
        acc.x += c0 * v0.x;
        acc.y += c0 * v0.y;
    }

    float c2 = dd * dd;
    float2 hv = __half22float2(h2v[(size_t)gw * 32 + lane]);
    float2 bb = ((const float2*)b2)[lane];
    float a = acc.x + c2 * hv.x + bb.x;
    float b = acc.y + c2 * hv.y + bb.y;

    float m = fmaxf(a, b);
    #pragma unroll
    for (int off = 16; off > 0; off >>= 1)
        m = fmaxf(m, __shfl_xor_sync(0xFFFFFFFFu, m, off));
    float s = expf(a - m) + expf(b - m);
    #pragma unroll
    for (int off = 16; off > 0; off >>= 1)
        s += __shfl_xor_sync(0xFFFFFFFFu, s, off);
    float l = m + logf(s);

    float2 o = make_float2(a - l, b - l);
    ((float2*)out)[(size_t)gw * 32 + lane] = o;
}

// ---------------- launch ----------------
// Fork/join inside graph capture:
//   side stream : deg_init+detect -> convert -> scans -> fill
//   dinv stream : dinv (after convert; parallel with scans)
//   main stream : wsplit -> GEMM1
// join all before agg1.
extern "C" void kernel_launch(void* const* d_in, const int* in_sizes, int n_in,
                              void* d_out, int out_size) {
    const float* x   = (const float*)d_in[0];
    const void*  ei  = (const void*)d_in[1];
    const float* W1  = (const float*)d_in[2];
    const float* b1  = (const float*)d_in[3];
    const float* W2  = (const float*)d_in[4];
    const float* b2  = (const float*)d_in[5];
    float*       out = (float*)d_out;

    static cudaStream_t s_side = nullptr, s_dv = nullptr;
    static cudaEvent_t  ev_fork = nullptr, ev_join = nullptr,
                        ev_cvt = nullptr, ev_dv = nullptr;
    if (s_side == nullptr) {
        cudaStreamCreateWithFlags(&s_side, cudaStreamNonBlocking);
        cudaStreamCreateWithFlags(&s_dv, cudaStreamNonBlocking);
        cudaEventCreateWithFlags(&ev_fork, cudaEventDisableTiming);
        cudaEventCreateWithFlags(&ev_join, cudaEventDisableTiming);
        cudaEventCreateWithFlags(&ev_cvt, cudaEventDisableTiming);
        cudaEventCreateWithFlags(&ev_dv, cudaEventDisableTiming);
    }

    // ---- fork: CSR chain on side stream ----
    cudaEventRecord(ev_fork, 0);
    cudaStreamWaitEvent(s_side, ev_fork, 0);
    k_deg_init_detect<<<(NN + 255) / 256, 256, 0, s_side>>>(ei);
    k_convert<<<(NE + 255) / 256, 256, 0, s_side>>>(ei);
    cudaEventRecord(ev_cvt, s_side);

    // dinv runs parallel with the scan chain
    cudaStreamWaitEvent(s_dv, ev_cvt, 0);
    k_dinv<<<(NN + 255) / 256, 256, 0, s_dv>>>();
    cudaEventRecord(ev_dv, s_dv);

    k_scan_partial<<<NBLK_SCAN, 1024, 0, s_side>>>();
    k_scan_base<<<1, 128, 0, s_side>>>();
    k_scan_write<<<NBLK_SCAN, 1024, 0, s_side>>>();
    k_fill<<<(NE + 255) / 256, 256, 0, s_side>>>(ei);
    cudaEventRecord(ev_join, s_side);

    // ---- main stream: weight split + layer-1 GEMM (independent of CSR) ----
    k_wsplit<<<(F0 * F1 + F1 * F2 + 255) / 256, 256>>>(W1, W2);
    const int NTILE = (NN + 127) / 128;
    k_mma1<<<NTILE, 256>>>(x);

    // ---- join, then the dependent tail ----
    cudaStreamWaitEvent(0, ev_join, 0);
    cudaStreamWaitEvent(0, ev_dv, 0);
    k_agg1<<<(NN * 32 + 255) / 256, 256>>>(b1);
    k_mma2<<<NTILE, 256>>>();
    k_agg2<<<(NN * 32 + 255) / 256, 256>>>(b2, out);
}

// round 11
// speedup vs baseline: 1.4057x; 1.0934x over previous
#include <cuda_runtime.h>
#include <cuda_bf16.h>
#include <cuda_fp16.h>
#include <cstdint>

#define NN 100000
#define NE 1600000
#define F0 256
#define F1 128
#define F2 64
#define NBLK_SCAN 98   // ceil(NN/1024)

// ---- scratch (device globals; no allocation allowed) ----
__device__ __align__(16) __half g_h1[NN * F1];   // x @ W1            (fp16 gather operand)
__device__ __align__(16) __half g_hr[NN * F1];   // relu(agg1+b1)     (fp16: GEMM2 A input)
__device__ __align__(16) __half g_h2[NN * F2];   // dinv*(hr @ W2)    (fp16, pre-scaled)
__device__ float g_dinv[NN];
__device__ int   g_deg[NN];
__device__ int   g_rowstart[NN];
__device__ int   g_cursor[NN];
__device__ int   g_csr[NE];
__device__ int   g_dst[NE];
__device__ int   g_is32;
__device__ int   g_part[128];
__device__ int   g_base[128];
// W1, W2 split into fp16 hi/lo (row-major [k][n])
__device__ __align__(16) __half g_w1h[F0 * F1];
__device__ __align__(16) __half g_w1l[F0 * F1];
__device__ __align__(16) __half g_w2h[F1 * F2];
__device__ __align__(16) __half g_w2l[F1 * F2];

// ================= mma.sync helpers (sm_80+ PTX; safe on base sm_103) =========
__device__ __forceinline__ uint32_t s2u(const void* p) {
    uint32_t a;
    asm("{ .reg .u64 t; cvta.to.shared.u64 t, %1; cvt.u32.u64 %0, t; }" : "=r"(a) : "l"(p));
    return a;
}

__device__ __forceinline__ void ldsm4(uint32_t* r, uint32_t a) {
    asm volatile("ldmatrix.sync.aligned.m8n8.x4.shared.b16 {%0,%1,%2,%3}, [%4];"
                 : "=r"(r[0]), "=r"(r[1]), "=r"(r[2]), "=r"(r[3]) : "r"(a));
}
__device__ __forceinline__ void ldsm4t(uint32_t* r, uint32_t a) {
    asm volatile("ldmatrix.sync.aligned.m8n8.x4.trans.shared.b16 {%0,%1,%2,%3}, [%4];"
                 : "=r"(r[0]), "=r"(r[1]), "=r"(r[2]), "=r"(r[3]) : "r"(a));
}
__device__ __forceinline__ void mma16816h(float* c, const uint32_t* a,
                                          uint32_t b0, uint32_t b1) {
    asm volatile("mma.sync.aligned.m16n8k16.row.col.f32.f16.f16.f32 "
                 "{%0,%1,%2,%3}, {%4,%5,%6,%7}, {%8,%9}, {%0,%1,%2,%3};"
                 : "+f"(c[0]), "+f"(c[1]), "+f"(c[2]), "+f"(c[3])
                 : "r"(a[0]), "r"(a[1]), "r"(a[2]), "r"(a[3]), "r"(b0), "r"(b1));
}

// -------- combined degree init + edge dtype detect --------
__global__ void k_deg_init_detect(const void* __restrict__ ei) {
    int i = blockIdx.x * blockDim.x + threadIdx.x;
    if (i < NN) g_deg[i] = 1;   // +1 self loop baked in
    if (i == 0) {
        const long long* e64 = (const long long*)ei;
        int ok64 = 1;
        for (int j = 0; j < 128; j++) {
            long long v = e64[j];
            if (v < 0 || v >= NN) { ok64 = 0; break; }
        }
        g_is32 = ok64 ? 0 : 1;
    }
}

__global__ void k_convert(const void* __restrict__ ei) {
    int i = blockIdx.x * blockDim.x + threadIdx.x;
    if (i >= NE) return;
    int v;
    if (g_is32) v = ((const int*)ei)[NE + i];
    else        v = (int)((const long long*)ei)[NE + i];
    g_dst[i] = v;
    if (v >= 0 && v < NN) atomicAdd(&g_deg[v], 1);   // fused degree count
}

__global__ void k_dinv() {
    int i = blockIdx.x * blockDim.x + threadIdx.x;
    if (i < NN) g_dinv[i] = rsqrtf((float)g_deg[i]);
}

// ---------------- W split to fp16 hi/lo ----------------
__global__ void k_wsplit(const float* __restrict__ W1, const float* __restrict__ W2) {
    int i = blockIdx.x * blockDim.x + threadIdx.x;
    if (i < F0 * F1) {
        float v = W1[i];
        __half h = __float2half_rn(v);
        g_w1h[i] = h;
        g_w1l[i] = __float2half_rn(v - __half2float(h));
    } else if (i < F0 * F1 + F1 * F2) {
        int j = i - F0 * F1;
        float v = W2[j];
        __half h = __float2half_rn(v);
        g_w2h[j] = h;
        g_w2l[j] = __float2half_rn(v - __half2float(h));
    }
}

// ---------------- CSR build: shfl-based scans, then cursor fill ----------------
__global__ void k_scan_partial() {
    int t = threadIdx.x;
    int i = blockIdx.x * 1024 + t;
    int v = (i < NN) ? (g_deg[i] - 1) : 0;
    #pragma unroll
    for (int o = 16; o > 0; o >>= 1) v += __shfl_xor_sync(0xFFFFFFFFu, v, o);
    __shared__ int ws[32];
    if ((t & 31) == 0) ws[t >> 5] = v;
    __syncthreads();
    if (t < 32) {
        int s = ws[t];
        #pragma unroll
        for (int o = 16; o > 0; o >>= 1) s += __shfl_xor_sync(0xFFFFFFFFu, s, o);
        if (t == 0) g_part[blockIdx.x] = s;
    }
}

__global__ void k_scan_base() {
    __shared__ int s[128];
    int t = threadIdx.x;
    int v = (t < NBLK_SCAN) ? g_part[t] : 0;
    s[t] = v;
    __syncthreads();
    for (int off = 1; off < 128; off <<= 1) {
        int u = (t >= off) ? s[t - off] : 0;
        __syncthreads();
        s[t] += u;
        __syncthreads();
    }
    if (t < NBLK_SCAN) g_base[t] = s[t] - v;  // exclusive
}

__global__ void k_scan_write() {
    int t = threadIdx.x, lane = t & 31, w = t >> 5;
    int i = blockIdx.x * 1024 + t;
    int v = (i < NN) ? (g_deg[i] - 1) : 0;
    int x = v;
    #pragma unroll
    for (int o = 1; o < 32; o <<= 1) {
        int u = __shfl_up_sync(0xFFFFFFFFu, x, o);
        if (lane >= o) x += u;
    }
    __shared__ int ws[32];
    if (lane == 31) ws[w] = x;
    __syncthreads();
    if (t < 32) {
        int s = ws[t];
        #pragma unroll
        for (int o = 1; o < 32; o <<= 1) {
            int u = __shfl_up_sync(0xFFFFFFFFu, s, o);
            if (lane >= o) s += u;
        }
        ws[t] = s;
    }
    __syncthreads();
    if (i < NN) {
        int base = g_base[blockIdx.x] + (w > 0 ? ws[w - 1] : 0);
        int start = base + x - v;   // exclusive prefix
        g_rowstart[i] = start;
        g_cursor[i]   = start;
    }
}

__global__ void k_fill(const void* __restrict__ ei) {
    int i = blockIdx.x * blockDim.x + threadIdx.x;
    if (i < NE) {
        int d = g_dst[i];
        if (d < 0 || d >= NN) return;
        int s;
        if (g_is32) s = ((const int*)ei)[i];
        else        s = (int)((const long long*)ei)[i];
        int pos = atomicAdd(&g_cursor[d], 1);
        if (pos >= 0 && pos < NE) g_csr[pos] = s;
    }
}

// =======================================================================
// GEMM1 (fp16 A exact, W1 split fp16 hi/lo, 2-pass):
//   g_h1[M,128](fp16) = x[M,256](fp32->fp16) @ W1
// CTA: 128 rows x 128 cols, 256 threads = 8 warps (4 M x 2 N). K chunk 32.
// =======================================================================
__global__ void __launch_bounds__(256, 2) k_mma1(const float* __restrict__ Ain) {
    constexpr int NC = F1, KT = F0;
    constexpr int KC   = 32;
    constexpr int AST  = 40;
    constexpr int BST  = NC + 8;     // 136
    constexpr int NWN  = NC / 2;     // 64
    constexpr int NT8  = NWN / 8;    // 8
    constexpr int NT16 = NWN / 16;   // 4
    constexpr int NC4  = NC / 4;     // 32 (uint2 per B row)

    __shared__ __align__(16) __half Ax[128 * AST];
    __shared__ __align__(16) __half Bh[KC * BST];
    __shared__ __align__(16) __half Bl[KC * BST];

    const int tid = threadIdx.x, lane = tid & 31, wid = tid >> 5;
    const int warp_m = wid & 3, warp_n = wid >> 2;
    const int rbase = blockIdx.x * 128;

    const uint32_t ax_b = s2u(Ax);
    const uint32_t bh_b = s2u(Bh), bl_b = s2u(Bl);

    float acc[2][NT8][4];
    #pragma unroll
    for (int a = 0; a < 2; a++)
        #pragma unroll
        for (int b = 0; b < NT8; b++)
            #pragma unroll
            for (int c = 0; c < 4; c++) acc[a][b][c] = 0.f;

    const int a_row = (lane & 15);
    const int a_col = 8 * (lane >> 4);
    const int b_row = (lane & 15);
    const int b_col = 8 * (lane >> 4);

    const float4* av = (const float4*)Ain;
    constexpr int ROWF4 = KT / 4;

    for (int ch = 0; ch < KT / KC; ch++) {
        const int c0 = ch * KC;

        // ---- stage A chunk: 128 x 32 fp32 -> fp16 (exact within fp16) ----
        #pragma unroll
        for (int i = 0; i < 4; i++) {
            int idx = tid + i * 256;            // 0..1023
            int r = idx >> 3;
            int f = idx & 7;                    // float4 within chunk
            float4 v = make_float4(0.f, 0.f, 0.f, 0.f);
            int gr = rbase + r;
            if (gr < NN) v = av[(size_t)gr * ROWF4 + (c0 >> 2) + f];
            uint2 p;
            *(__half2*)&p.x = __floats2half2_rn(v.x, v.y);
            *(__half2*)&p.y = __floats2half2_rn(v.z, v.w);
            *(uint2*)&Ax[r * AST + f * 4] = p;
        }

        // ---- stage B chunk: 32 x 128 fp16 hi/lo (uint2) ----
        #pragma unroll
        for (int i = 0; i < (KC * NC4) / 256; i++) {
            int idx = tid + i * 256;
            int k = idx / NC4, n4 = idx % NC4;
            int e = k * BST + n4 * 4;
            size_t ge = (size_t)(c0 + k) * NC + n4 * 4;
            *(uint2*)&Bh[e] = *(const uint2*)&g_w1h[ge];
            *(uint2*)&Bl[e] = *(const uint2*)&g_w1l[ge];
        }
        __syncthreads();

        #pragma unroll
        for (int ks = 0; ks < 2; ks++) {
            const int k16 = ks * 16;
            uint32_t af[2][4];
            #pragma unroll
            for (int mi = 0; mi < 2; mi++) {
                uint32_t off = (uint32_t)(((warp_m * 32 + mi * 16 + a_row) * AST
                                           + k16 + a_col) * 2);
                ldsm4(af[mi], ax_b + off);
            }
            #pragma unroll
            for (int ni = 0; ni < NT16; ni++) {
                uint32_t off = (uint32_t)(((k16 + b_row) * BST
                                           + warp_n * NWN + ni * 16 + b_col) * 2);
                uint32_t bfh[4], bfl[4];
                ldsm4t(bfh, bh_b + off);
                ldsm4t(bfl, bl_b + off);
                #pragma unroll
                for (int mi = 0; mi < 2; mi++) {
                    mma16816h(acc[mi][2 * ni],     af[mi], bfh[0], bfh[1]);  // A*hi
                    mma16816h(acc[mi][2 * ni + 1], af[mi], bfh[2], bfh[3]);
                    mma16816h(acc[mi][2 * ni],     af[mi], bfl[0], bfl[1]);  // A*lo
                    mma16816h(acc[mi][2 * ni + 1], af[mi], bfl[2], bfl[3]);
                }
            }
        }
        __syncthreads();
    }

    const int g = lane >> 2, tig = lane & 3;
    #pragma unroll
    for (int mi = 0; mi < 2; mi++) {
        int row0 = rbase + warp_m * 32 + mi * 16 + g;
        #pragma unroll
        for (int ni = 0; ni < NT8; ni++) {
            int col = warp_n * NWN + ni * 8 + tig * 2;
            if (row0 < NN)
                *(__half2*)&g_h1[(size_t)row0 * NC + col] =
                    __floats2half2_rn(acc[mi][ni][0], acc[mi][ni][1]);
            if (row0 + 8 < NN)
                *(__half2*)&g_h1[(size_t)(row0 + 8) * NC + col] =
                    __floats2half2_rn(acc[mi][ni][2], acc[mi][ni][3]);
        }
    }
}

// =======================================================================
// GEMM2 (fp16 A exact, W2 split fp16 hi/lo, 2-pass) + dinv pre-scale:
//   g_h2[M,64](fp16) = dinv[row] * (g_hr[M,128](fp16) @ W2)
// =======================================================================
__global__ void __launch_bounds__(256, 2) k_mma2() {
    constexpr int NC = F2, KT = F1;
    constexpr int KC   = 32;
    constexpr int AST  = 40;
    constexpr int BST  = NC + 8;     // 72
    constexpr int NWN  = NC / 2;     // 32
    constexpr int NT8  = NWN / 8;    // 4
    constexpr int NT16 = NWN / 16;   // 2
    constexpr int NC4  = NC / 4;     // 16

    __shared__ __align__(16) __half Ax[128 * AST];
    __shared__ __align__(16) __half Bh[KC * BST];
    __shared__ __align__(16) __half Bl[KC * BST];

    const int tid = threadIdx.x, lane = tid & 31, wid = tid >> 5;
    const int warp_m = wid & 3, warp_n = wid >> 2;
    const int rbase = blockIdx.x * 128;

    const uint32_t ax_b = s2u(Ax);
    const uint32_t bh_b = s2u(Bh), bl_b = s2u(Bl);

    float acc[2][NT8][4];
    #pragma unroll
    for (int a = 0; a < 2; a++)
        #pragma unroll
        for (int b = 0; b < NT8; b++)
            #pragma unroll
            for (int c = 0; c < 4; c++) acc[a][b][c] = 0.f;

    const int a_row = (lane & 15);
    const int a_col = 8 * (lane >> 4);
    const int b_row = (lane & 15);
    const int b_col = 8 * (lane >> 4);

    for (int ch = 0; ch < KT / KC; ch++) {
        const int c0 = ch * KC;

        #pragma unroll
        for (int i = 0; i < 4; i++) {
            int idx = tid + i * 256;
            int r = idx >> 3;
            int q = idx & 7;
            uint2 v = make_uint2(0u, 0u);
            int gr = rbase + r;
            if (gr < NN) v = *(const uint2*)&g_hr[(size_t)gr * KT + c0 + q * 4];
            *(uint2*)&Ax[r * AST + q * 4] = v;
        }

        #pragma unroll
        for (int i = 0; i < (KC * NC4) / 256; i++) {
            int idx = tid + i * 256;
            int k = idx / NC4, n4 = idx % NC4;
            int e = k * BST + n4 * 4;
            size_t ge = (size_t)(c0 + k) * NC + n4 * 4;
            *(uint2*)&Bh[e] = *(const uint2*)&g_w2h[ge];
            *(uint2*)&Bl[e] = *(const uint2*)&g_w2l[ge];
        }
        __syncthreads();

        #pragma unroll
        for (int ks = 0; ks < 2; ks++) {
            const int k16 = ks * 16;
            uint32_t af[2][4];
            #pragma unroll
            for (int mi = 0; mi < 2; mi++) {
                uint32_t off = (uint32_t)(((warp_m * 32 + mi * 16 + a_row) * AST
                                           + k16 + a_col) * 2);
                ldsm4(af[mi], ax_b + off);
            }
            #pragma unroll
            for (int ni = 0; ni < NT16; ni++) {
                uint32_t off = (uint32_t)(((k16 + b_row) * BST
                                           + warp_n * NWN + ni * 16 + b_col) * 2);
                uint32_t bfh[4], bfl[4];
                ldsm4t(bfh, bh_b + off);
                ldsm4t(bfl, bl_b + off);
                #pragma unroll
                for (int mi = 0; mi < 2; mi++) {
                    mma16816h(acc[mi][2 * ni],     af[mi], bfh[0], bfh[1]);
                    mma16816h(acc[mi][2 * ni + 1], af[mi], bfh[2], bfh[3]);
                    mma16816h(acc[mi][2 * ni],     af[mi], bfl[0], bfl[1]);
                    mma16816h(acc[mi][2 * ni + 1], af[mi], bfl[2], bfl[3]);
                }
            }
        }
        __syncthreads();
    }

    // ---- epilogue: pre-scale by dinv[row], write fp16 ----
    const int g = lane >> 2, tig = lane & 3;
    #pragma unroll
    for (int mi = 0; mi < 2; mi++) {
        int row0 = rbase + warp_m * 32 + mi * 16 + g;
        float dv0 = (row0 < NN) ? g_dinv[row0] : 0.f;
        float dv8 = (row0 + 8 < NN) ? g_dinv[row0 + 8] : 0.f;
        #pragma unroll
        for (int ni = 0; ni < NT8; ni++) {
            int col = warp_n * NWN + ni * 8 + tig * 2;
            if (row0 < NN)
                *(__half2*)&g_h2[(size_t)row0 * NC + col] =
                    __floats2half2_rn(acc[mi][ni][0] * dv0, acc[mi][ni][1] * dv0);
            if (row0 + 8 < NN)
                *(__half2*)&g_h2[(size_t)(row0 + 8) * NC + col] =
                    __floats2half2_rn(acc[mi][ni][2] * dv8, acc[mi][ni][3] * dv8);
        }
    }
}

// ---------------- Layer-1 aggregation (fp16 gather) + bias + ReLU -> fp16 ----------------
__global__ void k_agg1(const float* __restrict__ b1) {
    int gw   = (blockIdx.x * blockDim.x + threadIdx.x) >> 5;
    int lane = threadIdx.x & 31;
    if (gw >= NN) return;

    int start = g_rowstart[gw];
    int cnt   = g_deg[gw] - 1;
    float dd  = g_dinv[gw];

    const uint2* h1v = (const uint2*)g_h1;   // 32 uint2 per row (128 halves)
    float4 acc = make_float4(0.f, 0.f, 0.f, 0.f);

    int i = 0;
    for (; i + 1 < cnt; i += 2) {
        int s0 = g_csr[start + i];
        int s1 = g_csr[start + i + 1];
        float c0 = dd * g_dinv[s0];
        float c1 = dd * g_dinv[s1];
        uint2 r0 = h1v[(size_t)s0 * 32 + lane];
        uint2 r1 = h1v[(size_t)s1 * 32 + lane];
        float2 a0 = __half22float2(*(__half2*)&r0.x);
        float2 a1 = __half22float2(*(__half2*)&r0.y);
        float2 b0 = __half22float2(*(__half2*)&r1.x);
        float2 b1_ = __half22float2(*(__half2*)&r1.y);
        acc.x += c0 * a0.x + c1 * b0.x;
        acc.y += c0 * a0.y + c1 * b0.y;
        acc.z += c0 * a1.x + c1 * b1_.x;
        acc.w += c0 * a1.y + c1 * b1_.y;
    }
    if (i < cnt) {
        int s0 = g_csr[start + i];
        float c0 = dd * g_dinv[s0];
        uint2 r0 = h1v[(size_t)s0 * 32 + lane];
        float2 a0 = __half22float2(*(__half2*)&r0.x);
        float2 a1 = __half22float2(*(__half2*)&r0.y);
        acc.x += c0 * a0.x; acc.y += c0 * a0.y;
        acc.z += c0 * a1.x; acc.w += c0 * a1.y;
    }

    float c2 = dd * dd;
    uint2 rs = h1v[(size_t)gw * 32 + lane];
    float2 s0f = __half22float2(*(__half2*)&rs.x);
    float2 s1f = __half22float2(*(__half2*)&rs.y);
    float4 bb = ((const float4*)b1)[lane];
    float ox = fmaxf(acc.x + c2 * s0f.x + bb.x, 0.f);
    float oy = fmaxf(acc.y + c2 * s0f.y + bb.y, 0.f);
    float oz = fmaxf(acc.z + c2 * s1f.x + bb.z, 0.f);
    float ow = fmaxf(acc.w + c2 * s1f.y + bb.w, 0.f);

    uint2 ov;
    *(__half2*)&ov.x = __floats2half2_rn(ox, oy);
    *(__half2*)&ov.y = __floats2half2_rn(oz, ow);
    ((uint2*)g_hr)[(size_t)gw * 32 + lane] = ov;
}

// ---------------- Layer-2 aggregation (h2 pre-scaled by dinv) + bias + log_softmax ----
// agg = dd * (sum_src h2'[src] + h2'[self]) + b,  h2' = dinv*h2.
__global__ void k_agg2(const float* __restrict__ b2, float* __restrict__ out) {
    int gw   = (blockIdx.x * blockDim.x + threadIdx.x) >> 5;
    int lane = threadIdx.x & 31;
    if (gw >= NN) return;

    int start = g_rowstart[gw];
    int cnt   = g_deg[gw] - 1;
    float dd  = g_dinv[gw];

    const __half2* h2v = (const __half2*)g_h2;   // 32 half2 per row
    float2 acc = make_float2(0.f, 0.f);

    int i = 0;
    for (; i + 1 < cnt; i += 2) {
        int s0 = g_csr[start + i];
        int s1 = g_csr[start + i + 1];
        float2 v0 = __half22float2(h2v[(size_t)s0 * 32 + lane]);
        float2 v1 = __half22float2(h2v[(size_t)s1 * 32 + lane]);
        acc.x += v0.x + v1.x;
        acc.y += v0.y + v1.y;
    }
    if (i < cnt) {
        int s0 = g_csr[start + i];
        float2 v0 = __half22float2(h2v[(size_t)s0 * 32 + lane]);
        acc.x += v0.x;
        acc.y += v0.y;
    }

    float2 hv = __half22float2(h2v[(size_t)gw * 32 + lane]);
    float2 bb = ((const float2*)b2)[lane];
    float a = dd * (acc.x + hv.x) + bb.x;
    float b = dd * (acc.y + hv.y) + bb.y;

    float m = fmaxf(a, b);
    #pragma unroll
    for (int off = 16; off > 0; off >>= 1)
        m = fmaxf(m, __shfl_xor_sync(0xFFFFFFFFu, m, off));
    float s = expf(a - m) + expf(b - m);
    #pragma unroll
    for (int off = 16; off > 0; off >>= 1)
        s += __shfl_xor_sync(0xFFFFFFFFu, s, off);
    float l = m + logf(s);

    float2 o = make_float2(a - l, b - l);
    ((float2*)out)[(size_t)gw * 32 + lane] = o;
}

// ---------------- launch ----------------
extern "C" void kernel_launch(void* const* d_in, const int* in_sizes, int n_in,
                              void* d_out, int out_size) {
    const float* x   = (const float*)d_in[0];
    const void*  ei  = (const void*)d_in[1];
    const float* W1  = (const float*)d_in[2];
    const float* b1  = (const float*)d_in[3];
    const float* W2  = (const float*)d_in[4];
    const float* b2  = (const float*)d_in[5];
    float*       out = (float*)d_out;

    static cudaStream_t s_side = nullptr, s_dv = nullptr;
    static cudaEvent_t  ev_fork = nullptr, ev_join = nullptr,
                        ev_cvt = nullptr, ev_dv = nullptr;
    if (s_side == nullptr) {
        cudaStreamCreateWithFlags(&s_side, cudaStreamNonBlocking);
        cudaStreamCreateWithFlags(&s_dv, cudaStreamNonBlocking);
        cudaEventCreateWithFlags(&ev_fork, cudaEventDisableTiming);
        cudaEventCreateWithFlags(&ev_join, cudaEventDisableTiming);
        cudaEventCreateWithFlags(&ev_cvt, cudaEventDisableTiming);
        cudaEventCreateWithFlags(&ev_dv, cudaEventDisableTiming);
    }

    // ---- fork: CSR chain on side stream ----
    cudaEventRecord(ev_fork, 0);
    cudaStreamWaitEvent(s_side, ev_fork, 0);
    k_deg_init_detect<<<(NN + 255) / 256, 256, 0, s_side>>>(ei);
    k_convert<<<(NE + 255) / 256, 256, 0, s_side>>>(ei);
    cudaEventRecord(ev_cvt, s_side);

    // dinv runs parallel with the scan chain
    cudaStreamWaitEvent(s_dv, ev_cvt, 0);
    k_dinv<<<(NN + 255) / 256, 256, 0, s_dv>>>();
    cudaEventRecord(ev_dv, s_dv);

    k_scan_partial<<<NBLK_SCAN, 1024, 0, s_side>>>();
    k_scan_base<<<1, 128, 0, s_side>>>();
    k_scan_write<<<NBLK_SCAN, 1024, 0, s_side>>>();
    k_fill<<<(NE + 255) / 256, 256, 0, s_side>>>(ei);
    cudaEventRecord(ev_join, s_side);

    // ---- main stream: weight split + layer-1 GEMM (independent of CSR) ----
    k_wsplit<<<(F0 * F1 + F1 * F2 + 255) / 256, 256>>>(W1, W2);
    const int NTILE = (NN + 127) / 128;
    k_mma1<<<NTILE, 256>>>(x);

    // ---- join, then the dependent tail ----
    cudaStreamWaitEvent(0, ev_join, 0);
    cudaStreamWaitEvent(0, ev_dv, 0);
    k_agg1<<<(NN * 32 + 255) / 256, 256>>>(b1);
    k_mma2<<<NTILE, 256>>>();
    k_agg2<<<(NN * 32 + 255) / 256, 256>>>(b2, out);
}